// round 10
// baseline (speedup 1.0000x reference)
#include <cuda_runtime.h>
#include <cuda_bf16.h>
#include <math.h>
#include <stdint.h>

// Problem constants
#define BB 4
#define SS 4096
#define DD 2048
#define NH 16
#define HH 128
#define MTOT (BB * SS)   // 16384

// Chunked pipeline
#define NCH 8
#define CH  (SS / NCH)   // 512
#define HALF (CH / 2)    // 256 rows per GEMM half-launch

typedef unsigned long long ull;

// ---- packed fp32x2 helpers ----
__device__ __forceinline__ ull ffma2(ull a, ull b, ull c) {
    ull d;
    asm("fma.rn.f32x2 %0, %1, %2, %3;" : "=l"(d) : "l"(a), "l"(b), "l"(c));
    return d;
}
__device__ __forceinline__ ull addf2(ull a, ull b) {
    ull d;
    asm("add.rn.f32x2 %0, %1, %2;" : "=l"(d) : "l"(a), "l"(b));
    return d;
}
__device__ __forceinline__ ull pack2(float lo, float hi) {
    ull r;
    asm("mov.b64 %0, {%1, %2};" : "=l"(r) : "f"(lo), "f"(hi));
    return r;
}
__device__ __forceinline__ void unpack2(ull v, float& lo, float& hi) {
    asm("mov.b64 {%0, %1}, %2;" : "=f"(lo), "=f"(hi) : "l"(v));
}
__device__ __forceinline__ uint32_t smem_u32(const void* p) {
    uint32_t a;
    asm("{ .reg .u64 t; cvta.to.shared.u64 t, %1; cvt.u32.u64 %0, t; }" : "=r"(a) : "l"(p));
    return a;
}

// fast tanh: (e^{2x}-1)/(e^{2x}+1) via MUFU ex2/rcp; rel err ~1e-7
__device__ __forceinline__ float fast_tanh(float x) {
    float t = fminf(x * 2.885390081777927f, 80.0f);
    float e;
    asm("ex2.approx.f32 %0, %1;" : "=f"(e) : "f"(t));
    float r;
    asm("rcp.approx.f32 %0, %1;" : "=f"(r) : "f"(e + 1.0f));
    return (e - 1.0f) * r;
}

// ---- mma.sync / ldmatrix / cp.async (plain PTX, assembles at compute_103) ----
__device__ __forceinline__ void ldsm4(uint32_t* r, uint32_t addr) {
    asm volatile("ldmatrix.sync.aligned.m8n8.x4.shared.b16 {%0,%1,%2,%3}, [%4];"
                 : "=r"(r[0]), "=r"(r[1]), "=r"(r[2]), "=r"(r[3]) : "r"(addr));
}
__device__ __forceinline__ void ldsm4t(uint32_t* r, uint32_t addr) {
    asm volatile("ldmatrix.sync.aligned.m8n8.x4.trans.shared.b16 {%0,%1,%2,%3}, [%4];"
                 : "=r"(r[0]), "=r"(r[1]), "=r"(r[2]), "=r"(r[3]) : "r"(addr));
}
__device__ __forceinline__ void mma_bf16(float* c, const uint32_t* a, uint32_t b0, uint32_t b1) {
    asm volatile("mma.sync.aligned.m16n8k16.row.col.f32.bf16.bf16.f32 "
                 "{%0,%1,%2,%3}, {%4,%5,%6,%7}, {%8,%9}, {%0,%1,%2,%3};"
                 : "+f"(c[0]), "+f"(c[1]), "+f"(c[2]), "+f"(c[3])
                 : "r"(a[0]), "r"(a[1]), "r"(a[2]), "r"(a[3]), "r"(b0), "r"(b1));
}
__device__ __forceinline__ void cp_async16(uint32_t saddr, const void* gaddr) {
    asm volatile("cp.async.cg.shared.global [%0], [%1], 16;"
                 :: "r"(saddr), "l"(gaddr) : "memory");
}

// ---- scratch (device globals; no allocation allowed) ----
__device__ float g_x[33554432];                               // (B,S,D) post-input-projection fp32
__device__ __nv_bfloat16 g_inhi[33554432], g_inlo[33554432];  // input split
__device__ __nv_bfloat16 g_yhi[33554432],  g_ylo[33554432];   // scan output split
__device__ __nv_bfloat16 g_wihi[4194304],  g_wilo[4194304];   // w_in split
__device__ __nv_bfloat16 g_wohi[4194304],  g_wolo[4194304];   // w_out split
__device__ float g_state[BB * NH * HH];

// ============================================================================
// fp32 -> bf16 hi/lo split (elementwise, float4 per thread)
// ============================================================================
__device__ __forceinline__ void split4(const float* __restrict__ src,
                                       __nv_bfloat16* __restrict__ hi,
                                       __nv_bfloat16* __restrict__ lo, size_t i) {
    float4 v = ((const float4*)src)[i];
    float f[4] = {v.x, v.y, v.z, v.w};
    uint32_t hw[4], lw[4];
    #pragma unroll
    for (int j = 0; j < 4; j++) {
        __nv_bfloat16 h = __float2bfloat16(f[j]);
        float r = f[j] - __bfloat162float(h);
        __nv_bfloat16 l = __float2bfloat16(r);
        hw[j] = *(unsigned short*)&h;
        lw[j] = *(unsigned short*)&l;
    }
    *(uint2*)(hi + 4 * i) = make_uint2(hw[0] | (hw[1] << 16), hw[2] | (hw[3] << 16));
    *(uint2*)(lo + 4 * i) = make_uint2(lw[0] | (lw[1] << 16), lw[2] | (lw[3] << 16));
}

__global__ __launch_bounds__(256)
void cvt_split_kernel(const float* __restrict__ src,
                      __nv_bfloat16* __restrict__ hi,
                      __nv_bfloat16* __restrict__ lo, int n4) {
    int i = blockIdx.x * 256 + threadIdx.x;
    if (i < n4) split4(src, hi, lo, (size_t)i);
}

// Per-chunk input split: blockIdx.z = b, covers rows [s_base, s_base+CH) of batch b
__global__ __launch_bounds__(256)
void cvt_split_chunk_kernel(const float* __restrict__ src,
                            __nv_bfloat16* __restrict__ hi,
                            __nv_bfloat16* __restrict__ lo, int s_base) {
    size_t base4 = (((size_t)blockIdx.z * SS + s_base) * DD) >> 2;
    size_t i = base4 + blockIdx.x * 256 + threadIdx.x;
    split4(src, hi, lo, i);
}

// ============================================================================
// bf16 3-product-split GEMM, pre-converted operands, cp.async 3-stage pipeline.
// Tile 128x128, BK=32, 256 threads = 8 warps (4M x 2N), 2 CTAs/SM (96KB x2 =
// 192KB < 227KB). Launched as 128-CTA half-grids so >=168 of 296 CTA slots
// stay free for the concurrent scan chain.
// ============================================================================
#define AHI 0
#define ALO 8192
#define BHI 16384
#define BLO 24576
#define STAGE 32768
#define NSTG 3

__device__ __forceinline__ uint32_t aoff(int r, int c) {
    return (uint32_t)(r * 64 + ((c ^ ((r >> 1) & 3)) * 16));
}
__device__ __forceinline__ uint32_t boff(int kr, int c) {
    return (uint32_t)(kr * 256 + ((c ^ (kr & 7)) * 16));
}

__global__ __launch_bounds__(256, 2)
void gemm_mma_kernel(const __nv_bfloat16* __restrict__ Ahi, const __nv_bfloat16* __restrict__ Alo,
                     const __nv_bfloat16* __restrict__ Bhi, const __nv_bfloat16* __restrict__ Blo,
                     const float* __restrict__ bias, float* __restrict__ C, int s_base) {
    extern __shared__ __align__(128) char smem[];
    const uint32_t sb = smem_u32(smem);

    const int t    = threadIdx.x;
    const int lane = t & 31;
    const int wid  = t >> 5;
    const int wm   = wid >> 1;
    const int wn   = wid & 1;
    const size_t m0 = (size_t)blockIdx.z * SS + (size_t)s_base + (size_t)blockIdx.y * 128;
    const size_t n0 = (size_t)blockIdx.x * 128;

    const int ar = t >> 2, ac = t & 3;
    const int br = t >> 4, bc = t & 15;
    const __nv_bfloat16* pAh = Ahi + (m0 + ar) * DD + ac * 8;
    const __nv_bfloat16* pAl = Alo + (m0 + ar) * DD + ac * 8;
    const __nv_bfloat16* pBh = Bhi + (size_t)br * DD + n0 + bc * 8;
    const __nv_bfloat16* pBl = Blo + (size_t)br * DD + n0 + bc * 8;
    const uint32_t sA0 = AHI + aoff(ar, ac);
    const uint32_t sA1 = AHI + aoff(ar + 64, ac);
    const uint32_t sB0 = BHI + boff(br, bc);
    const uint32_t sB1 = BHI + boff(br + 16, bc);

    const int arow = wm * 32 + (lane & 7) + ((lane >> 3) & 1) * 8;
    const int akh  = (lane >> 4) & 1;
    uint32_t aAo[2][2];
    #pragma unroll
    for (int mt = 0; mt < 2; mt++)
        #pragma unroll
        for (int ks = 0; ks < 2; ks++)
            aAo[mt][ks] = AHI + aoff(arow + mt * 16, ks * 2 + akh);
    const int bpair = lane >> 4;
    const int bkr0  = ((lane >> 3) & 1) * 8 + (lane & 7);
    uint32_t aBo[2][4];
    #pragma unroll
    for (int ks = 0; ks < 2; ks++)
        #pragma unroll
        for (int bq = 0; bq < 4; bq++)
            aBo[ks][bq] = BHI + boff(ks * 16 + bkr0, wn * 8 + bq * 2 + bpair);

    float acc[2][8][4];
    #pragma unroll
    for (int mt = 0; mt < 2; mt++)
        #pragma unroll
        for (int nt = 0; nt < 8; nt++)
            #pragma unroll
            for (int i = 0; i < 4; i++) acc[mt][nt][i] = 0.0f;

    auto load_stage = [&](int stg, int k0) {
        const uint32_t s = sb + (uint32_t)stg * STAGE;
        cp_async16(s + sA0, pAh + k0);
        cp_async16(s + sA1, pAh + (size_t)64 * DD + k0);
        cp_async16(s + sA0 + (ALO - AHI), pAl + k0);
        cp_async16(s + sA1 + (ALO - AHI), pAl + (size_t)64 * DD + k0);
        cp_async16(s + sB0, pBh + (size_t)k0 * DD);
        cp_async16(s + sB1, pBh + (size_t)(k0 + 16) * DD);
        cp_async16(s + sB0 + (BLO - BHI), pBl + (size_t)k0 * DD);
        cp_async16(s + sB1 + (BLO - BHI), pBl + (size_t)(k0 + 16) * DD);
    };

    // prologue: tiles 0,1 into stages 0,1
    load_stage(0, 0);
    asm volatile("cp.async.commit_group;" ::: "memory");
    load_stage(1, 32);
    asm volatile("cp.async.commit_group;" ::: "memory");

    for (int tile = 0; tile < 64; tile++) {
        if (tile + 2 < 64) load_stage((tile + 2) % 3, (tile + 2) * 32);
        asm volatile("cp.async.commit_group;" ::: "memory");   // empty groups keep counting exact
        asm volatile("cp.async.wait_group 2;" ::: "memory");
        __syncthreads();

        const uint32_t stg = sb + (uint32_t)(tile % 3) * STAGE;
        #pragma unroll
        for (int ks = 0; ks < 2; ks++) {
            uint32_t ah[2][4], al[2][4], bx[4][4];
            ldsm4(ah[0], stg + aAo[0][ks]);
            ldsm4(ah[1], stg + aAo[1][ks]);
            ldsm4(al[0], stg + aAo[0][ks] + (ALO - AHI));
            ldsm4(al[1], stg + aAo[1][ks] + (ALO - AHI));
            #pragma unroll
            for (int bq = 0; bq < 4; bq++) ldsm4t(bx[bq], stg + aBo[ks][bq]);

            #pragma unroll
            for (int mt = 0; mt < 2; mt++)
                #pragma unroll
                for (int nt = 0; nt < 8; nt++) {
                    const int bq = nt >> 1, of = (nt & 1) * 2;
                    mma_bf16(acc[mt][nt], ah[mt], bx[bq][of], bx[bq][of + 1]);
                }
            #pragma unroll
            for (int mt = 0; mt < 2; mt++)
                #pragma unroll
                for (int nt = 0; nt < 8; nt++) {
                    const int bq = nt >> 1, of = (nt & 1) * 2;
                    mma_bf16(acc[mt][nt], al[mt], bx[bq][of], bx[bq][of + 1]);
                }
            // reload bx <- B_lo (reuses registers)
            #pragma unroll
            for (int bq = 0; bq < 4; bq++) ldsm4t(bx[bq], stg + aBo[ks][bq] + (BLO - BHI));
            #pragma unroll
            for (int mt = 0; mt < 2; mt++)
                #pragma unroll
                for (int nt = 0; nt < 8; nt++) {
                    const int bq = nt >> 1, of = (nt & 1) * 2;
                    mma_bf16(acc[mt][nt], ah[mt], bx[bq][of], bx[bq][of + 1]);
                }
        }
        __syncthreads();
    }

    const int g  = lane >> 2;
    const int tc = lane & 3;
    #pragma unroll
    for (int mt = 0; mt < 2; mt++) {
        const size_t row0 = m0 + wm * 32 + mt * 16 + g;
        #pragma unroll
        for (int nt = 0; nt < 8; nt++) {
            const size_t col = n0 + wn * 64 + nt * 8 + tc * 2;
            float b0 = 0.0f, b1 = 0.0f;
            if (bias != nullptr) { b0 = bias[col]; b1 = bias[col + 1]; }
            float2 v0 = make_float2(acc[mt][nt][0] + b0, acc[mt][nt][1] + b1);
            float2 v1 = make_float2(acc[mt][nt][2] + b0, acc[mt][nt][3] + b1);
            *(float2*)(C + row0 * DD + col)       = v0;
            *(float2*)(C + (row0 + 8) * DD + col) = v1;
        }
    }
}

// ============================================================================
// Scan chunk: steps [s_base, s_base+s_len). 64 blocks, one per (b, n).
// Emits y directly as bf16 hi/lo. Runs in the >=168 free CTA slots.
// ============================================================================
__global__ __launch_bounds__(128, 1)
void scan_kernel(const float* __restrict__ x, const float* __restrict__ sin,
                 const float* __restrict__ SW,
                 __nv_bfloat16* __restrict__ yhi, __nv_bfloat16* __restrict__ ylo,
                 float* __restrict__ sfin, int s_base, int s_len) {
    const int b = blockIdx.x >> 4;
    const int n = blockIdx.x & 15;
    const int k = threadIdx.x;

    const float* Wn = SW + (size_t)n * HH * HH;
    ull w2[64];
    #pragma unroll
    for (int j = 0; j < 64; j++)
        w2[j] = pack2(Wn[(2 * j) * HH + k], Wn[(2 * j + 1) * HH + k]);

    __shared__ __align__(16) float sbuf[2][HH];
    sbuf[0][k] = sin[((size_t)b * NH + n) * HH + k];
    __syncthreads();

    const float* xp = x + ((size_t)b * SS + s_base) * DD + n * HH + k;
    __nv_bfloat16* yhp = yhi + ((size_t)b * SS + s_base) * DD + n * HH + k;
    __nv_bfloat16* ylp = ylo + ((size_t)b * SS + s_base) * DD + n * HH + k;

    float xa = xp[0];
    float xb = xp[DD];
    float xc = xp[2 * (size_t)DD];
    float v = 0.0f;

    for (int t = 0; t < s_len; t++) {
        float xn = 0.0f;
        if (t + 3 < s_len) xn = xp[(size_t)(t + 3) * DD];

        const ulonglong2* s4 = (const ulonglong2*)sbuf[t & 1];
        ull a0 = 0ull, a1 = 0ull, a2 = 0ull, a3 = 0ull;
        ull a4 = 0ull, a5 = 0ull, a6 = 0ull, a7 = 0ull;
        #pragma unroll
        for (int j = 0; j < 8; j++) {
            ulonglong2 p = s4[4 * j];
            ulonglong2 q = s4[4 * j + 1];
            ulonglong2 r = s4[4 * j + 2];
            ulonglong2 s = s4[4 * j + 3];
            a0 = ffma2(p.x, w2[8 * j + 0], a0);
            a1 = ffma2(p.y, w2[8 * j + 1], a1);
            a2 = ffma2(q.x, w2[8 * j + 2], a2);
            a3 = ffma2(q.y, w2[8 * j + 3], a3);
            a4 = ffma2(r.x, w2[8 * j + 4], a4);
            a5 = ffma2(r.y, w2[8 * j + 5], a5);
            a6 = ffma2(s.x, w2[8 * j + 6], a6);
            a7 = ffma2(s.y, w2[8 * j + 7], a7);
        }
        ull s01 = addf2(a0, a1), s23 = addf2(a2, a3);
        ull s45 = addf2(a4, a5), s67 = addf2(a6, a7);
        ull sall = addf2(addf2(s01, s23), addf2(s45, s67));
        float lo, hi;
        unpack2(sall, lo, hi);
        float dot = lo + hi;

        v = fast_tanh(dot + xa);
        __nv_bfloat16 h = __float2bfloat16(v);
        yhp[(size_t)t * DD] = h;
        ylp[(size_t)t * DD] = __float2bfloat16(v - __bfloat162float(h));
        sbuf[(t + 1) & 1][k] = v;

        xa = xb; xb = xc; xc = xn;
        __syncthreads();
    }

    sfin[((size_t)b * NH + n) * HH + k] = v;
}

// ============================================================================
// Launch: chunked prelude + 3-stream pipeline with 128-CTA GEMM half-grids.
//   origin: [cvt_c, gin_c(x2 halves)] x8    st1 (hi prio): scan_c    st2: gout_c(x2)
// ============================================================================
extern "C" void kernel_launch(void* const* d_in, const int* in_sizes, int n_in,
                              void* d_out, int out_size) {
    const float* input  = (const float*)d_in[0];
    const float* state0 = (const float*)d_in[1];
    const float* w_in   = (const float*)d_in[2];
    const float* b_in   = (const float*)d_in[3];
    const float* sw     = (const float*)d_in[4];
    const float* w_out  = (const float*)d_in[5];
    float* out = (float*)d_out;

    float *xbuf, *stbuf;
    __nv_bfloat16 *inhi, *inlo, *yhi, *ylo, *wihi, *wilo, *wohi, *wolo;
    cudaGetSymbolAddress((void**)&xbuf, g_x);
    cudaGetSymbolAddress((void**)&stbuf, g_state);
    cudaGetSymbolAddress((void**)&inhi, g_inhi);
    cudaGetSymbolAddress((void**)&inlo, g_inlo);
    cudaGetSymbolAddress((void**)&yhi, g_yhi);
    cudaGetSymbolAddress((void**)&ylo, g_ylo);
    cudaGetSymbolAddress((void**)&wihi, g_wihi);
    cudaGetSymbolAddress((void**)&wilo, g_wilo);
    cudaGetSymbolAddress((void**)&wohi, g_wohi);
    cudaGetSymbolAddress((void**)&wolo, g_wolo);

    static cudaStream_t st1 = nullptr, st2 = nullptr;
    static cudaEvent_t ev_gin[NCH], ev_scan[NCH], ev_root, ev_w, ev_tail;
    if (st1 == nullptr) {
        int prio_lo, prio_hi;
        cudaDeviceGetStreamPriorityRange(&prio_lo, &prio_hi);
        cudaStreamCreateWithPriority(&st1, cudaStreamNonBlocking, prio_hi);  // scan: highest
        cudaStreamCreateWithFlags(&st2, cudaStreamNonBlocking);
        for (int c = 0; c < NCH; c++) {
            cudaEventCreateWithFlags(&ev_gin[c], cudaEventDisableTiming);
            cudaEventCreateWithFlags(&ev_scan[c], cudaEventDisableTiming);
        }
        cudaEventCreateWithFlags(&ev_root, cudaEventDisableTiming);
        cudaEventCreateWithFlags(&ev_w, cudaEventDisableTiming);
        cudaEventCreateWithFlags(&ev_tail, cudaEventDisableTiming);
    }

    const int smem_bytes = NSTG * STAGE;  // 98304; x2 CTAs = 192KB < 227KB
    cudaFuncSetAttribute(gemm_mma_kernel, cudaFuncAttributeMaxDynamicSharedMemorySize, smem_bytes);

    // ---- prelude: weight splits on st2 ----
    cudaEventRecord(ev_root, 0);
    cudaStreamWaitEvent(st2, ev_root, 0);
    cvt_split_kernel<<<4096, 256, 0, st2>>>(w_in, wihi, wilo, DD * DD / 4);
    cvt_split_kernel<<<4096, 256, 0, st2>>>(w_out, wohi, wolo, DD * DD / 4);
    cudaEventRecord(ev_w, st2);
    cudaStreamWaitEvent(0, ev_w, 0);

    dim3 hgrid(DD / 128, HALF / 128, BB);  // (16, 2, 4) = 128 CTAs per half
    dim3 cgrid(CH * DD / 4 / 256, 1, BB);  // (1024, 1, 4) per chunk

    // Input split + input-projection (two 128-CTA halves), chunk by chunk
    for (int c = 0; c < NCH; c++) {
        cvt_split_chunk_kernel<<<cgrid, 256>>>(input, inhi, inlo, c * CH);
        gemm_mma_kernel<<<hgrid, 256, smem_bytes>>>(inhi, inlo, wihi, wilo, b_in, xbuf, c * CH);
        gemm_mma_kernel<<<hgrid, 256, smem_bytes>>>(inhi, inlo, wihi, wilo, b_in, xbuf, c * CH + HALF);
        cudaEventRecord(ev_gin[c], 0);
    }

    // Scan chunks on high-priority stream (sequential by state dependency)
    for (int c = 0; c < NCH; c++) {
        cudaStreamWaitEvent(st1, ev_gin[c], 0);
        const float* s_init = (c == 0) ? state0 : stbuf;
        scan_kernel<<<BB * NH, HH, 0, st1>>>(xbuf, s_init, sw, yhi, ylo, stbuf, c * CH, CH);
        cudaEventRecord(ev_scan[c], st1);
    }

    // Output-projection chunks on st2 (two 128-CTA halves each)
    for (int c = 0; c < NCH; c++) {
        cudaStreamWaitEvent(st2, ev_scan[c], 0);
        gemm_mma_kernel<<<hgrid, 256, smem_bytes, st2>>>(yhi, ylo, wohi, wolo, nullptr, out, c * CH);
        gemm_mma_kernel<<<hgrid, 256, smem_bytes, st2>>>(yhi, ylo, wohi, wolo, nullptr, out, c * CH + HALF);
    }

    // Join forked work back to origin stream for graph capture
    cudaEventRecord(ev_tail, st2);
    cudaStreamWaitEvent(0, ev_tail, 0);
}

// round 11
// speedup vs baseline: 1.0191x; 1.0191x over previous
#include <cuda_runtime.h>
#include <cuda_bf16.h>
#include <math.h>
#include <stdint.h>

// Problem constants
#define BB 4
#define SS 4096
#define DD 2048
#define NH 16
#define HH 128
#define MTOT (BB * SS)   // 16384

// Chunked pipeline
#define NCH 8
#define CH  (SS / NCH)   // 512

typedef unsigned long long ull;

// ---- packed fp32x2 helpers ----
__device__ __forceinline__ ull ffma2(ull a, ull b, ull c) {
    ull d;
    asm("fma.rn.f32x2 %0, %1, %2, %3;" : "=l"(d) : "l"(a), "l"(b), "l"(c));
    return d;
}
__device__ __forceinline__ ull addf2(ull a, ull b) {
    ull d;
    asm("add.rn.f32x2 %0, %1, %2;" : "=l"(d) : "l"(a), "l"(b));
    return d;
}
__device__ __forceinline__ ull pack2(float lo, float hi) {
    ull r;
    asm("mov.b64 %0, {%1, %2};" : "=l"(r) : "f"(lo), "f"(hi));
    return r;
}
__device__ __forceinline__ void unpack2(ull v, float& lo, float& hi) {
    asm("mov.b64 {%0, %1}, %2;" : "=f"(lo), "=f"(hi) : "l"(v));
}
__device__ __forceinline__ uint32_t smem_u32(const void* p) {
    uint32_t a;
    asm("{ .reg .u64 t; cvta.to.shared.u64 t, %1; cvt.u32.u64 %0, t; }" : "=r"(a) : "l"(p));
    return a;
}

// fast tanh: (e^{2x}-1)/(e^{2x}+1) via MUFU ex2/rcp; rel err ~1e-7
__device__ __forceinline__ float fast_tanh(float x) {
    float t = fminf(x * 2.885390081777927f, 80.0f);
    float e;
    asm("ex2.approx.f32 %0, %1;" : "=f"(e) : "f"(t));
    float r;
    asm("rcp.approx.f32 %0, %1;" : "=f"(r) : "f"(e + 1.0f));
    return (e - 1.0f) * r;
}

// ---- mma.sync / ldmatrix / cp.async (plain PTX, assembles at compute_103) ----
__device__ __forceinline__ void ldsm4(uint32_t* r, uint32_t addr) {
    asm volatile("ldmatrix.sync.aligned.m8n8.x4.shared.b16 {%0,%1,%2,%3}, [%4];"
                 : "=r"(r[0]), "=r"(r[1]), "=r"(r[2]), "=r"(r[3]) : "r"(addr));
}
__device__ __forceinline__ void ldsm4t(uint32_t* r, uint32_t addr) {
    asm volatile("ldmatrix.sync.aligned.m8n8.x4.trans.shared.b16 {%0,%1,%2,%3}, [%4];"
                 : "=r"(r[0]), "=r"(r[1]), "=r"(r[2]), "=r"(r[3]) : "r"(addr));
}
__device__ __forceinline__ void mma_bf16(float* c, const uint32_t* a, uint32_t b0, uint32_t b1) {
    asm volatile("mma.sync.aligned.m16n8k16.row.col.f32.bf16.bf16.f32 "
                 "{%0,%1,%2,%3}, {%4,%5,%6,%7}, {%8,%9}, {%0,%1,%2,%3};"
                 : "+f"(c[0]), "+f"(c[1]), "+f"(c[2]), "+f"(c[3])
                 : "r"(a[0]), "r"(a[1]), "r"(a[2]), "r"(a[3]), "r"(b0), "r"(b1));
}
__device__ __forceinline__ void cp_async16(uint32_t saddr, const void* gaddr) {
    asm volatile("cp.async.cg.shared.global [%0], [%1], 16;"
                 :: "r"(saddr), "l"(gaddr) : "memory");
}

// ---- scratch (device globals; no allocation allowed) ----
__device__ float g_x[33554432];                               // (B,S,D) post-input-projection fp32
__device__ __nv_bfloat16 g_inhi[33554432], g_inlo[33554432];  // input split
__device__ __nv_bfloat16 g_yhi[33554432],  g_ylo[33554432];   // scan output split
__device__ __nv_bfloat16 g_wihi[4194304],  g_wilo[4194304];   // w_in split
__device__ __nv_bfloat16 g_wohi[4194304],  g_wolo[4194304];   // w_out split
__device__ float g_state[BB * NH * HH];

// ============================================================================
// fp32 -> bf16 hi/lo split (elementwise, float4 per thread)
// ============================================================================
__device__ __forceinline__ void split4(const float* __restrict__ src,
                                       __nv_bfloat16* __restrict__ hi,
                                       __nv_bfloat16* __restrict__ lo, size_t i) {
    float4 v = ((const float4*)src)[i];
    float f[4] = {v.x, v.y, v.z, v.w};
    uint32_t hw[4], lw[4];
    #pragma unroll
    for (int j = 0; j < 4; j++) {
        __nv_bfloat16 h = __float2bfloat16(f[j]);
        float r = f[j] - __bfloat162float(h);
        __nv_bfloat16 l = __float2bfloat16(r);
        hw[j] = *(unsigned short*)&h;
        lw[j] = *(unsigned short*)&l;
    }
    *(uint2*)(hi + 4 * i) = make_uint2(hw[0] | (hw[1] << 16), hw[2] | (hw[3] << 16));
    *(uint2*)(lo + 4 * i) = make_uint2(lw[0] | (lw[1] << 16), lw[2] | (lw[3] << 16));
}

__global__ __launch_bounds__(256)
void cvt_split_kernel(const float* __restrict__ src,
                      __nv_bfloat16* __restrict__ hi,
                      __nv_bfloat16* __restrict__ lo, int n4) {
    int i = blockIdx.x * 256 + threadIdx.x;
    if (i < n4) split4(src, hi, lo, (size_t)i);
}

// Per-chunk input split: blockIdx.z = b, covers rows [s_base, s_base+CH) of batch b
__global__ __launch_bounds__(256)
void cvt_split_chunk_kernel(const float* __restrict__ src,
                            __nv_bfloat16* __restrict__ hi,
                            __nv_bfloat16* __restrict__ lo, int s_base) {
    size_t base4 = (((size_t)blockIdx.z * SS + s_base) * DD) >> 2;
    size_t i = base4 + blockIdx.x * 256 + threadIdx.x;
    split4(src, hi, lo, i);
}

// ============================================================================
// bf16 3-product-split GEMM (R8 config: best measured machine time).
// Tile 128x128, BK=32, 256 threads = 8 warps (4M x 2N), 3-stage cp.async,
// 96KB dyn smem, 2 CTAs/SM. Full 256-CTA chunk grids.
// ============================================================================
#define AHI 0
#define ALO 8192
#define BHI 16384
#define BLO 24576
#define STAGE 32768
#define NSTG 3

__device__ __forceinline__ uint32_t aoff(int r, int c) {
    return (uint32_t)(r * 64 + ((c ^ ((r >> 1) & 3)) * 16));
}
__device__ __forceinline__ uint32_t boff(int kr, int c) {
    return (uint32_t)(kr * 256 + ((c ^ (kr & 7)) * 16));
}

__global__ __launch_bounds__(256, 2)
void gemm_mma_kernel(const __nv_bfloat16* __restrict__ Ahi, const __nv_bfloat16* __restrict__ Alo,
                     const __nv_bfloat16* __restrict__ Bhi, const __nv_bfloat16* __restrict__ Blo,
                     const float* __restrict__ bias, float* __restrict__ C, int s_base) {
    extern __shared__ __align__(128) char smem[];
    const uint32_t sb = smem_u32(smem);

    const int t    = threadIdx.x;
    const int lane = t & 31;
    const int wid  = t >> 5;
    const int wm   = wid >> 1;
    const int wn   = wid & 1;
    const size_t m0 = (size_t)blockIdx.z * SS + (size_t)s_base + (size_t)blockIdx.y * 128;
    const size_t n0 = (size_t)blockIdx.x * 128;

    const int ar = t >> 2, ac = t & 3;
    const int br = t >> 4, bc = t & 15;
    const __nv_bfloat16* pAh = Ahi + (m0 + ar) * DD + ac * 8;
    const __nv_bfloat16* pAl = Alo + (m0 + ar) * DD + ac * 8;
    const __nv_bfloat16* pBh = Bhi + (size_t)br * DD + n0 + bc * 8;
    const __nv_bfloat16* pBl = Blo + (size_t)br * DD + n0 + bc * 8;
    const uint32_t sA0 = AHI + aoff(ar, ac);
    const uint32_t sA1 = AHI + aoff(ar + 64, ac);
    const uint32_t sB0 = BHI + boff(br, bc);
    const uint32_t sB1 = BHI + boff(br + 16, bc);

    const int arow = wm * 32 + (lane & 7) + ((lane >> 3) & 1) * 8;
    const int akh  = (lane >> 4) & 1;
    uint32_t aAo[2][2];
    #pragma unroll
    for (int mt = 0; mt < 2; mt++)
        #pragma unroll
        for (int ks = 0; ks < 2; ks++)
            aAo[mt][ks] = AHI + aoff(arow + mt * 16, ks * 2 + akh);
    const int bpair = lane >> 4;
    const int bkr0  = ((lane >> 3) & 1) * 8 + (lane & 7);
    uint32_t aBo[2][4];
    #pragma unroll
    for (int ks = 0; ks < 2; ks++)
        #pragma unroll
        for (int bq = 0; bq < 4; bq++)
            aBo[ks][bq] = BHI + boff(ks * 16 + bkr0, wn * 8 + bq * 2 + bpair);

    float acc[2][8][4];
    #pragma unroll
    for (int mt = 0; mt < 2; mt++)
        #pragma unroll
        for (int nt = 0; nt < 8; nt++)
            #pragma unroll
            for (int i = 0; i < 4; i++) acc[mt][nt][i] = 0.0f;

    auto load_stage = [&](int stg, int k0) {
        const uint32_t s = sb + (uint32_t)stg * STAGE;
        cp_async16(s + sA0, pAh + k0);
        cp_async16(s + sA1, pAh + (size_t)64 * DD + k0);
        cp_async16(s + sA0 + (ALO - AHI), pAl + k0);
        cp_async16(s + sA1 + (ALO - AHI), pAl + (size_t)64 * DD + k0);
        cp_async16(s + sB0, pBh + (size_t)k0 * DD);
        cp_async16(s + sB1, pBh + (size_t)(k0 + 16) * DD);
        cp_async16(s + sB0 + (BLO - BHI), pBl + (size_t)k0 * DD);
        cp_async16(s + sB1 + (BLO - BHI), pBl + (size_t)(k0 + 16) * DD);
    };

    // prologue: tiles 0,1 into stages 0,1
    load_stage(0, 0);
    asm volatile("cp.async.commit_group;" ::: "memory");
    load_stage(1, 32);
    asm volatile("cp.async.commit_group;" ::: "memory");

    for (int tile = 0; tile < 64; tile++) {
        if (tile + 2 < 64) load_stage((tile + 2) % 3, (tile + 2) * 32);
        asm volatile("cp.async.commit_group;" ::: "memory");   // empty groups keep counting exact
        asm volatile("cp.async.wait_group 2;" ::: "memory");
        __syncthreads();

        const uint32_t stg = sb + (uint32_t)(tile % 3) * STAGE;
        #pragma unroll
        for (int ks = 0; ks < 2; ks++) {
            uint32_t ah[2][4], al[2][4], bx[4][4];
            ldsm4(ah[0], stg + aAo[0][ks]);
            ldsm4(ah[1], stg + aAo[1][ks]);
            ldsm4(al[0], stg + aAo[0][ks] + (ALO - AHI));
            ldsm4(al[1], stg + aAo[1][ks] + (ALO - AHI));
            #pragma unroll
            for (int bq = 0; bq < 4; bq++) ldsm4t(bx[bq], stg + aBo[ks][bq]);

            #pragma unroll
            for (int mt = 0; mt < 2; mt++)
                #pragma unroll
                for (int nt = 0; nt < 8; nt++) {
                    const int bq = nt >> 1, of = (nt & 1) * 2;
                    mma_bf16(acc[mt][nt], ah[mt], bx[bq][of], bx[bq][of + 1]);
                }
            #pragma unroll
            for (int mt = 0; mt < 2; mt++)
                #pragma unroll
                for (int nt = 0; nt < 8; nt++) {
                    const int bq = nt >> 1, of = (nt & 1) * 2;
                    mma_bf16(acc[mt][nt], al[mt], bx[bq][of], bx[bq][of + 1]);
                }
            // reload bx <- B_lo (reuses registers)
            #pragma unroll
            for (int bq = 0; bq < 4; bq++) ldsm4t(bx[bq], stg + aBo[ks][bq] + (BLO - BHI));
            #pragma unroll
            for (int mt = 0; mt < 2; mt++)
                #pragma unroll
                for (int nt = 0; nt < 8; nt++) {
                    const int bq = nt >> 1, of = (nt & 1) * 2;
                    mma_bf16(acc[mt][nt], ah[mt], bx[bq][of], bx[bq][of + 1]);
                }
        }
        __syncthreads();
    }

    const int g  = lane >> 2;
    const int tc = lane & 3;
    #pragma unroll
    for (int mt = 0; mt < 2; mt++) {
        const size_t row0 = m0 + wm * 32 + mt * 16 + g;
        #pragma unroll
        for (int nt = 0; nt < 8; nt++) {
            const size_t col = n0 + wn * 64 + nt * 8 + tc * 2;
            float b0 = 0.0f, b1 = 0.0f;
            if (bias != nullptr) { b0 = bias[col]; b1 = bias[col + 1]; }
            float2 v0 = make_float2(acc[mt][nt][0] + b0, acc[mt][nt][1] + b1);
            float2 v1 = make_float2(acc[mt][nt][2] + b0, acc[mt][nt][3] + b1);
            *(float2*)(C + row0 * DD + col)       = v0;
            *(float2*)(C + (row0 + 8) * DD + col) = v1;
        }
    }
}

// ============================================================================
// Scan chunk, 256-thread split-K: thread (k, half) computes a 64-element
// partial dot (32 FFMA2, 4 accs); halves combine through one smem word.
// 2 warps/SMSP interleave to hide LDS/MUFU/RAW stalls. 64 blocks, one per (b,n).
// ============================================================================
__global__ __launch_bounds__(256, 1)
void scan_kernel(const float* __restrict__ x, const float* __restrict__ sin,
                 const float* __restrict__ SW,
                 __nv_bfloat16* __restrict__ yhi, __nv_bfloat16* __restrict__ ylo,
                 float* __restrict__ sfin, int s_base, int s_len) {
    const int b = blockIdx.x >> 4;
    const int n = blockIdx.x & 15;
    const int tt = threadIdx.x;
    const int k = tt & 127;
    const int half = tt >> 7;   // 0: h rows 0..63, 1: h rows 64..127

    // W column k of head n, rows [half*64, half*64+64), packed in (even,odd) pairs
    const float* Wn = SW + (size_t)n * HH * HH;
    ull w2[32];
    #pragma unroll
    for (int j = 0; j < 32; j++)
        w2[j] = pack2(Wn[(half * 64 + 2 * j) * HH + k], Wn[(half * 64 + 2 * j + 1) * HH + k]);

    __shared__ __align__(16) float sbuf[2][HH];
    __shared__ __align__(16) float psum[HH];
    if (half == 0) sbuf[0][k] = sin[((size_t)b * NH + n) * HH + k];
    __syncthreads();

    const float* xp = x + ((size_t)b * SS + s_base) * DD + n * HH + k;
    __nv_bfloat16* yhp = yhi + ((size_t)b * SS + s_base) * DD + n * HH + k;
    __nv_bfloat16* ylp = ylo + ((size_t)b * SS + s_base) * DD + n * HH + k;

    float xa = 0.0f, xb = 0.0f, xc = 0.0f;
    if (half == 0) {
        xa = xp[0];
        xb = xp[DD];
        xc = xp[2 * (size_t)DD];
    }
    float v = 0.0f;

    for (int t = 0; t < s_len; t++) {
        float xn = 0.0f;
        if (half == 0 && t + 3 < s_len) xn = xp[(size_t)(t + 3) * DD];

        // 64-element partial: 16 ulonglong2 loads (broadcast), 32 FFMA2, 4 accs
        const ulonglong2* s4 = (const ulonglong2*)(sbuf[t & 1] + half * 64);
        ull a0 = 0ull, a1 = 0ull, a2 = 0ull, a3 = 0ull;
        #pragma unroll
        for (int j = 0; j < 4; j++) {
            ulonglong2 p = s4[4 * j];
            ulonglong2 q = s4[4 * j + 1];
            ulonglong2 r = s4[4 * j + 2];
            ulonglong2 s = s4[4 * j + 3];
            a0 = ffma2(p.x, w2[8 * j + 0], a0);
            a1 = ffma2(p.y, w2[8 * j + 1], a1);
            a2 = ffma2(q.x, w2[8 * j + 2], a2);
            a3 = ffma2(q.y, w2[8 * j + 3], a3);
            a0 = ffma2(r.x, w2[8 * j + 4], a0);
            a1 = ffma2(r.y, w2[8 * j + 5], a1);
            a2 = ffma2(s.x, w2[8 * j + 6], a2);
            a3 = ffma2(s.y, w2[8 * j + 7], a3);
        }
        ull s01 = addf2(a0, a1), s23 = addf2(a2, a3);
        ull sall = addf2(s01, s23);
        float plo, phi;
        unpack2(sall, plo, phi);
        float part = plo + phi;

        if (half) psum[k] = part;
        __syncthreads();

        if (!half) {
            float dot = part + psum[k];
            v = fast_tanh(dot + xa);
            __nv_bfloat16 h = __float2bfloat16(v);
            yhp[(size_t)t * DD] = h;
            ylp[(size_t)t * DD] = __float2bfloat16(v - __bfloat162float(h));
            sbuf[(t + 1) & 1][k] = v;
            xa = xb; xb = xc; xc = xn;
        }
        __syncthreads();
    }

    if (half == 0) sfin[((size_t)b * NH + n) * HH + k] = v;
}

// ============================================================================
// Launch: chunked prelude + 3-stream pipeline (R8 structure, R9 chunked cvt).
//   origin: [cvt_c, gin_c] x8     st1 (hi prio): scan_c     st2: gout_c
// ============================================================================
extern "C" void kernel_launch(void* const* d_in, const int* in_sizes, int n_in,
                              void* d_out, int out_size) {
    const float* input  = (const float*)d_in[0];
    const float* state0 = (const float*)d_in[1];
    const float* w_in   = (const float*)d_in[2];
    const float* b_in   = (const float*)d_in[3];
    const float* sw     = (const float*)d_in[4];
    const float* w_out  = (const float*)d_in[5];
    float* out = (float*)d_out;

    float *xbuf, *stbuf;
    __nv_bfloat16 *inhi, *inlo, *yhi, *ylo, *wihi, *wilo, *wohi, *wolo;
    cudaGetSymbolAddress((void**)&xbuf, g_x);
    cudaGetSymbolAddress((void**)&stbuf, g_state);
    cudaGetSymbolAddress((void**)&inhi, g_inhi);
    cudaGetSymbolAddress((void**)&inlo, g_inlo);
    cudaGetSymbolAddress((void**)&yhi, g_yhi);
    cudaGetSymbolAddress((void**)&ylo, g_ylo);
    cudaGetSymbolAddress((void**)&wihi, g_wihi);
    cudaGetSymbolAddress((void**)&wilo, g_wilo);
    cudaGetSymbolAddress((void**)&wohi, g_wohi);
    cudaGetSymbolAddress((void**)&wolo, g_wolo);

    static cudaStream_t st1 = nullptr, st2 = nullptr;
    static cudaEvent_t ev_gin[NCH], ev_scan[NCH], ev_root, ev_w, ev_tail;
    if (st1 == nullptr) {
        int prio_lo, prio_hi;
        cudaDeviceGetStreamPriorityRange(&prio_lo, &prio_hi);
        cudaStreamCreateWithPriority(&st1, cudaStreamNonBlocking, prio_hi);  // scan: highest
        cudaStreamCreateWithFlags(&st2, cudaStreamNonBlocking);
        for (int c = 0; c < NCH; c++) {
            cudaEventCreateWithFlags(&ev_gin[c], cudaEventDisableTiming);
            cudaEventCreateWithFlags(&ev_scan[c], cudaEventDisableTiming);
        }
        cudaEventCreateWithFlags(&ev_root, cudaEventDisableTiming);
        cudaEventCreateWithFlags(&ev_w, cudaEventDisableTiming);
        cudaEventCreateWithFlags(&ev_tail, cudaEventDisableTiming);
    }

    const int smem_bytes = NSTG * STAGE;  // 98304; x2 CTAs = 192KB < 227KB
    cudaFuncSetAttribute(gemm_mma_kernel, cudaFuncAttributeMaxDynamicSharedMemorySize, smem_bytes);

    // ---- prelude: weight splits on st2 (overlap chunk-0 input split) ----
    cudaEventRecord(ev_root, 0);
    cudaStreamWaitEvent(st2, ev_root, 0);
    cvt_split_kernel<<<4096, 256, 0, st2>>>(w_in, wihi, wilo, DD * DD / 4);
    cvt_split_kernel<<<4096, 256, 0, st2>>>(w_out, wohi, wolo, DD * DD / 4);
    cudaEventRecord(ev_w, st2);
    cudaStreamWaitEvent(0, ev_w, 0);

    dim3 ggrid(DD / 128, CH / 128, BB);    // (16, 4, 4) = 256 CTAs per chunk
    dim3 cgrid(CH * DD / 4 / 256, 1, BB);  // (1024, 1, 4) per chunk

    // Input split + input-projection, chunk by chunk, on origin stream
    for (int c = 0; c < NCH; c++) {
        cvt_split_chunk_kernel<<<cgrid, 256>>>(input, inhi, inlo, c * CH);
        gemm_mma_kernel<<<ggrid, 256, smem_bytes>>>(inhi, inlo, wihi, wilo, b_in, xbuf, c * CH);
        cudaEventRecord(ev_gin[c], 0);
    }

    // Scan chunks on high-priority stream (sequential by state dependency)
    for (int c = 0; c < NCH; c++) {
        cudaStreamWaitEvent(st1, ev_gin[c], 0);
        const float* s_init = (c == 0) ? state0 : stbuf;
        scan_kernel<<<BB * NH, 256, 0, st1>>>(xbuf, s_init, sw, yhi, ylo, stbuf, c * CH, CH);
        cudaEventRecord(ev_scan[c], st1);
    }

    // Output-projection chunks on st2
    for (int c = 0; c < NCH; c++) {
        cudaStreamWaitEvent(st2, ev_scan[c], 0);
        gemm_mma_kernel<<<ggrid, 256, smem_bytes, st2>>>(yhi, ylo, wohi, wolo, nullptr, out, c * CH);
    }

    // Join forked work back to origin stream for graph capture
    cudaEventRecord(ev_tail, st2);
    cudaStreamWaitEvent(0, ev_tail, 0);
}

// round 14
// speedup vs baseline: 1.0664x; 1.0464x over previous
#include <cuda_runtime.h>
#include <cuda_bf16.h>
#include <math.h>
#include <stdint.h>

// Problem constants
#define BB 4
#define SS 4096
#define DD 2048
#define NH 16
#define HH 128
#define MTOT (BB * SS)   // 16384

// Chunked pipeline
#define NCH 8
#define CH  (SS / NCH)   // 512

typedef unsigned long long ull;

// ---- packed fp32x2 helpers ----
__device__ __forceinline__ ull ffma2(ull a, ull b, ull c) {
    ull d;
    asm("fma.rn.f32x2 %0, %1, %2, %3;" : "=l"(d) : "l"(a), "l"(b), "l"(c));
    return d;
}
__device__ __forceinline__ ull addf2(ull a, ull b) {
    ull d;
    asm("add.rn.f32x2 %0, %1, %2;" : "=l"(d) : "l"(a), "l"(b));
    return d;
}
__device__ __forceinline__ ull pack2(float lo, float hi) {
    ull r;
    asm("mov.b64 %0, {%1, %2};" : "=l"(r) : "f"(lo), "f"(hi));
    return r;
}
__device__ __forceinline__ void unpack2(ull v, float& lo, float& hi) {
    asm("mov.b64 {%0, %1}, %2;" : "=f"(lo), "=f"(hi) : "l"(v));
}
__device__ __forceinline__ uint32_t smem_u32(const void* p) {
    uint32_t a;
    asm("{ .reg .u64 t; cvta.to.shared.u64 t, %1; cvt.u32.u64 %0, t; }" : "=r"(a) : "l"(p));
    return a;
}

// fast tanh: (e^{2x}-1)/(e^{2x}+1) via MUFU ex2/rcp; rel err ~1e-7
__device__ __forceinline__ float fast_tanh(float x) {
    float t = fminf(x * 2.885390081777927f, 80.0f);
    float e;
    asm("ex2.approx.f32 %0, %1;" : "=f"(e) : "f"(t));
    float r;
    asm("rcp.approx.f32 %0, %1;" : "=f"(r) : "f"(e + 1.0f));
    return (e - 1.0f) * r;
}

// ---- mma.sync / ldmatrix / cp.async (plain PTX, assembles at compute_103) ----
__device__ __forceinline__ void ldsm4(uint32_t* r, uint32_t addr) {
    asm volatile("ldmatrix.sync.aligned.m8n8.x4.shared.b16 {%0,%1,%2,%3}, [%4];"
                 : "=r"(r[0]), "=r"(r[1]), "=r"(r[2]), "=r"(r[3]) : "r"(addr));
}
__device__ __forceinline__ void ldsm4t(uint32_t* r, uint32_t addr) {
    asm volatile("ldmatrix.sync.aligned.m8n8.x4.trans.shared.b16 {%0,%1,%2,%3}, [%4];"
                 : "=r"(r[0]), "=r"(r[1]), "=r"(r[2]), "=r"(r[3]) : "r"(addr));
}
__device__ __forceinline__ void mma_bf16(float* c, const uint32_t* a, uint32_t b0, uint32_t b1) {
    asm volatile("mma.sync.aligned.m16n8k16.row.col.f32.bf16.bf16.f32 "
                 "{%0,%1,%2,%3}, {%4,%5,%6,%7}, {%8,%9}, {%0,%1,%2,%3};"
                 : "+f"(c[0]), "+f"(c[1]), "+f"(c[2]), "+f"(c[3])
                 : "r"(a[0]), "r"(a[1]), "r"(a[2]), "r"(a[3]), "r"(b0), "r"(b1));
}
__device__ __forceinline__ void cp_async16(uint32_t saddr, const void* gaddr) {
    asm volatile("cp.async.cg.shared.global [%0], [%1], 16;"
                 :: "r"(saddr), "l"(gaddr) : "memory");
}

// ---- scratch (device globals; no allocation allowed) ----
__device__ float g_x[33554432];                               // (B,S,D) post-input-projection fp32
__device__ __nv_bfloat16 g_yhi[33554432],  g_ylo[33554432];   // scan output split
__device__ __nv_bfloat16 g_wihi[4194304],  g_wilo[4194304];   // w_in split
__device__ __nv_bfloat16 g_wohi[4194304],  g_wolo[4194304];   // w_out split
__device__ float g_state[BB * NH * HH];

// ============================================================================
// fp32 -> bf16 hi/lo split (weights only now)
// ============================================================================
__global__ __launch_bounds__(256)
void cvt_split_kernel(const float* __restrict__ src,
                      __nv_bfloat16* __restrict__ hi,
                      __nv_bfloat16* __restrict__ lo, int n4) {
    int i = blockIdx.x * 256 + threadIdx.x;
    if (i >= n4) return;
    float4 v = ((const float4*)src)[i];
    float f[4] = {v.x, v.y, v.z, v.w};
    uint32_t hw[4], lw[4];
    #pragma unroll
    for (int j = 0; j < 4; j++) {
        __nv_bfloat16 h = __float2bfloat16(f[j]);
        float r = f[j] - __bfloat162float(h);
        __nv_bfloat16 l = __float2bfloat16(r);
        hw[j] = *(unsigned short*)&h;
        lw[j] = *(unsigned short*)&l;
    }
    *(uint2*)(hi + 4 * (size_t)i) = make_uint2(hw[0] | (hw[1] << 16), hw[2] | (hw[3] << 16));
    *(uint2*)(lo + 4 * (size_t)i) = make_uint2(lw[0] | (lw[1] << 16), lw[2] | (lw[3] << 16));
}

// ============================================================================
// Shared tiling helpers
// ============================================================================
__device__ __forceinline__ uint32_t aoff(int r, int c) {
    return (uint32_t)(r * 64 + ((c ^ ((r >> 1) & 3)) * 16));
}
__device__ __forceinline__ uint32_t boff(int kr, int c) {
    return (uint32_t)(kr * 256 + ((c ^ (kr & 7)) * 16));
}

// convert 8 fp32 -> 8 bf16 hi + 8 bf16 lo, store both to smem (16B each)
__device__ __forceinline__ void cvt_store(uint32_t dhi, uint32_t dlo, float4 v0, float4 v1) {
    float f[8] = {v0.x, v0.y, v0.z, v0.w, v1.x, v1.y, v1.z, v1.w};
    uint32_t h[4], l[4];
    #pragma unroll
    for (int p = 0; p < 4; p++) {
        uint32_t hp;
        asm("cvt.rn.bf16x2.f32 %0, %1, %2;" : "=r"(hp) : "f"(f[2 * p + 1]), "f"(f[2 * p]));
        float h0 = __uint_as_float(hp << 16);
        float h1 = __uint_as_float(hp & 0xFFFF0000u);
        float l0 = f[2 * p] - h0;
        float l1 = f[2 * p + 1] - h1;
        uint32_t lp;
        asm("cvt.rn.bf16x2.f32 %0, %1, %2;" : "=r"(lp) : "f"(l1), "f"(l0));
        h[p] = hp; l[p] = lp;
    }
    asm volatile("st.shared.v4.b32 [%0], {%1,%2,%3,%4};"
                 :: "r"(dhi), "r"(h[0]), "r"(h[1]), "r"(h[2]), "r"(h[3]));
    asm volatile("st.shared.v4.b32 [%0], {%1,%2,%3,%4};"
                 :: "r"(dlo), "r"(l[0]), "r"(l[1]), "r"(l[2]), "r"(l[3]));
}

// Shared MMA core: 3-pass (ahi*bhi + alo*bhi + ahi*blo) for one BK=32 tile.
// A lo plane at abase+8192; B lo plane at bbase+8192.
struct Frag { float acc[2][8][4]; };

__device__ __forceinline__ void mma_tile(Frag& fr, uint32_t abase, uint32_t bbase,
                                         const uint32_t aAo[2][2], const uint32_t aBo[2][4]) {
    #pragma unroll
    for (int ks = 0; ks < 2; ks++) {
        uint32_t ah[2][4], al[2][4], bx[4][4];
        ldsm4(ah[0], abase + aAo[0][ks]);
        ldsm4(ah[1], abase + aAo[1][ks]);
        ldsm4(al[0], abase + aAo[0][ks] + 8192);
        ldsm4(al[1], abase + aAo[1][ks] + 8192);
        #pragma unroll
        for (int bq = 0; bq < 4; bq++) ldsm4t(bx[bq], bbase + aBo[ks][bq]);

        #pragma unroll
        for (int mt = 0; mt < 2; mt++)
            #pragma unroll
            for (int nt = 0; nt < 8; nt++) {
                const int bq = nt >> 1, of = (nt & 1) * 2;
                mma_bf16(fr.acc[mt][nt], ah[mt], bx[bq][of], bx[bq][of + 1]);
            }
        #pragma unroll
        for (int mt = 0; mt < 2; mt++)
            #pragma unroll
            for (int nt = 0; nt < 8; nt++) {
                const int bq = nt >> 1, of = (nt & 1) * 2;
                mma_bf16(fr.acc[mt][nt], al[mt], bx[bq][of], bx[bq][of + 1]);
            }
        #pragma unroll
        for (int bq = 0; bq < 4; bq++) ldsm4t(bx[bq], bbase + aBo[ks][bq] + 8192);
        #pragma unroll
        for (int mt = 0; mt < 2; mt++)
            #pragma unroll
            for (int nt = 0; nt < 8; nt++) {
                const int bq = nt >> 1, of = (nt & 1) * 2;
                mma_bf16(fr.acc[mt][nt], ah[mt], bx[bq][of], bx[bq][of + 1]);
            }
    }
}

__device__ __forceinline__ void epilogue(const Frag& fr, float* C, const float* bias,
                                         size_t m0, size_t n0, int wm, int wn, int lane) {
    const int g  = lane >> 2;
    const int tc = lane & 3;
    #pragma unroll
    for (int mt = 0; mt < 2; mt++) {
        const size_t row0 = m0 + wm * 32 + mt * 16 + g;
        #pragma unroll
        for (int nt = 0; nt < 8; nt++) {
            const size_t col = n0 + wn * 64 + nt * 8 + tc * 2;
            float b0 = 0.0f, b1 = 0.0f;
            if (bias != nullptr) { b0 = bias[col]; b1 = bias[col + 1]; }
            float2 v0 = make_float2(fr.acc[mt][nt][0] + b0, fr.acc[mt][nt][1] + b1);
            float2 v1 = make_float2(fr.acc[mt][nt][2] + b0, fr.acc[mt][nt][3] + b1);
            *(float2*)(C + row0 * DD + col)       = v0;
            *(float2*)(C + (row0 + 8) * DD + col) = v1;
        }
    }
}

// ============================================================================
// gout GEMM (R8 config): both operands pre-split bf16, 3-stage cp.async,
// 96KB dyn smem, 2 CTAs/SM. Stage (32KB): Ahi@0, Alo@8K, Bhi@16K, Blo@24K.
// ============================================================================
#define STAGE 32768

__global__ __launch_bounds__(256, 2)
void gemm_mma_kernel(const __nv_bfloat16* __restrict__ Ahi, const __nv_bfloat16* __restrict__ Alo,
                     const __nv_bfloat16* __restrict__ Bhi, const __nv_bfloat16* __restrict__ Blo,
                     const float* __restrict__ bias, float* __restrict__ C, int s_base) {
    extern __shared__ __align__(128) char smem[];
    const uint32_t sb = smem_u32(smem);

    const int t    = threadIdx.x;
    const int lane = t & 31;
    const int wid  = t >> 5;
    const int wm   = wid >> 1;
    const int wn   = wid & 1;
    const size_t m0 = (size_t)blockIdx.z * SS + (size_t)s_base + (size_t)blockIdx.y * 128;
    const size_t n0 = (size_t)blockIdx.x * 128;

    const int ar = t >> 2, ac = t & 3;
    const int br = t >> 4, bc = t & 15;
    const __nv_bfloat16* pAh = Ahi + (m0 + ar) * DD + ac * 8;
    const __nv_bfloat16* pAl = Alo + (m0 + ar) * DD + ac * 8;
    const __nv_bfloat16* pBh = Bhi + (size_t)br * DD + n0 + bc * 8;
    const __nv_bfloat16* pBl = Blo + (size_t)br * DD + n0 + bc * 8;
    const uint32_t sA0 = aoff(ar, ac);
    const uint32_t sA1 = aoff(ar + 64, ac);
    const uint32_t sB0 = 16384 + boff(br, bc);
    const uint32_t sB1 = 16384 + boff(br + 16, bc);

    const int arow = wm * 32 + (lane & 7) + ((lane >> 3) & 1) * 8;
    const int akh  = (lane >> 4) & 1;
    uint32_t aAo[2][2];
    #pragma unroll
    for (int mt = 0; mt < 2; mt++)
        #pragma unroll
        for (int ks = 0; ks < 2; ks++)
            aAo[mt][ks] = aoff(arow + mt * 16, ks * 2 + akh);
    const int bpair = lane >> 4;
    const int bkr0  = ((lane >> 3) & 1) * 8 + (lane & 7);
    uint32_t aBo[2][4];
    #pragma unroll
    for (int ks = 0; ks < 2; ks++)
        #pragma unroll
        for (int bq = 0; bq < 4; bq++)
            aBo[ks][bq] = boff(ks * 16 + bkr0, wn * 8 + bq * 2 + bpair);

    Frag fr;
    #pragma unroll
    for (int mt = 0; mt < 2; mt++)
        #pragma unroll
        for (int nt = 0; nt < 8; nt++)
            #pragma unroll
            for (int i = 0; i < 4; i++) fr.acc[mt][nt][i] = 0.0f;

    auto load_stage = [&](int stg, int k0) {
        const uint32_t s = sb + (uint32_t)stg * STAGE;
        cp_async16(s + sA0, pAh + k0);
        cp_async16(s + sA1, pAh + (size_t)64 * DD + k0);
        cp_async16(s + sA0 + 8192, pAl + k0);
        cp_async16(s + sA1 + 8192, pAl + (size_t)64 * DD + k0);
        cp_async16(s + sB0, pBh + (size_t)k0 * DD);
        cp_async16(s + sB1, pBh + (size_t)(k0 + 16) * DD);
        cp_async16(s + sB0 + 8192, pBl + (size_t)k0 * DD);
        cp_async16(s + sB1 + 8192, pBl + (size_t)(k0 + 16) * DD);
    };

    load_stage(0, 0);
    asm volatile("cp.async.commit_group;" ::: "memory");
    load_stage(1, 32);
    asm volatile("cp.async.commit_group;" ::: "memory");

    for (int tile = 0; tile < 64; tile++) {
        if (tile + 2 < 64) load_stage((tile + 2) % 3, (tile + 2) * 32);
        asm volatile("cp.async.commit_group;" ::: "memory");
        asm volatile("cp.async.wait_group 2;" ::: "memory");
        __syncthreads();

        const uint32_t stg = sb + (uint32_t)(tile % 3) * STAGE;
        mma_tile(fr, stg, stg + 16384, aAo, aBo);
        __syncthreads();
    }

    epilogue(fr, C, bias, m0, n0, wm, wn, lane);
}

// ============================================================================
// gin hybrid GEMM: A = raw fp32 input (LDG -> hi/lo cvt -> STS, double-buffered),
// B = pre-split bf16 weights via 3-stage cp.async. No input prelude needed.
// smem: A 2 x 16KB @ {0, 16K}; B 3 x 16KB @ {32K, 48K, 64K} = 80KB, 2 CTAs/SM.
// ============================================================================
#define HB_ABUF 16384
#define HB_BBASE 32768
#define HB_BSTG 16384

__global__ __launch_bounds__(256, 2)
void gemm_hybrid_kernel(const float* __restrict__ A,
                        const __nv_bfloat16* __restrict__ Bhi, const __nv_bfloat16* __restrict__ Blo,
                        const float* __restrict__ bias, float* __restrict__ C, int s_base) {
    extern __shared__ __align__(128) char smem[];
    const uint32_t sb = smem_u32(smem);

    const int t    = threadIdx.x;
    const int lane = t & 31;
    const int wid  = t >> 5;
    const int wm   = wid >> 1;
    const int wn   = wid & 1;
    const size_t m0 = (size_t)blockIdx.z * SS + (size_t)s_base + (size_t)blockIdx.y * 128;
    const size_t n0 = (size_t)blockIdx.x * 128;

    const int ar = t >> 2, ac = t & 3;
    const int br = t >> 4, bc = t & 15;
    const float* pA = A + (m0 + ar) * DD + ac * 8;   // fp32
    const __nv_bfloat16* pBh = Bhi + (size_t)br * DD + n0 + bc * 8;
    const __nv_bfloat16* pBl = Blo + (size_t)br * DD + n0 + bc * 8;
    const uint32_t sA0 = aoff(ar, ac);
    const uint32_t sA1 = aoff(ar + 64, ac);
    const uint32_t sB0 = HB_BBASE + boff(br, bc);
    const uint32_t sB1 = HB_BBASE + boff(br + 16, bc);

    const int arow = wm * 32 + (lane & 7) + ((lane >> 3) & 1) * 8;
    const int akh  = (lane >> 4) & 1;
    uint32_t aAo[2][2];
    #pragma unroll
    for (int mt = 0; mt < 2; mt++)
        #pragma unroll
        for (int ks = 0; ks < 2; ks++)
            aAo[mt][ks] = aoff(arow + mt * 16, ks * 2 + akh);
    const int bpair = lane >> 4;
    const int bkr0  = ((lane >> 3) & 1) * 8 + (lane & 7);
    uint32_t aBo[2][4];
    #pragma unroll
    for (int ks = 0; ks < 2; ks++)
        #pragma unroll
        for (int bq = 0; bq < 4; bq++)
            aBo[ks][bq] = boff(ks * 16 + bkr0, wn * 8 + bq * 2 + bpair);

    Frag fr;
    #pragma unroll
    for (int mt = 0; mt < 2; mt++)
        #pragma unroll
        for (int nt = 0; nt < 8; nt++)
            #pragma unroll
            for (int i = 0; i < 4; i++) fr.acc[mt][nt][i] = 0.0f;

    auto load_b_stage = [&](int stg, int k0) {
        const uint32_t off = (uint32_t)stg * HB_BSTG;
        cp_async16(sb + sB0 + off, pBh + (size_t)k0 * DD);
        cp_async16(sb + sB1 + off, pBh + (size_t)(k0 + 16) * DD);
        cp_async16(sb + sB0 + off + 8192, pBl + (size_t)k0 * DD);
        cp_async16(sb + sB1 + off + 8192, pBl + (size_t)(k0 + 16) * DD);
    };

    // ---- prologue ----
    float4 rA0a = *(const float4*)(pA);
    float4 rA0b = *(const float4*)(pA + 4);
    float4 rA1a = *(const float4*)(pA + (size_t)64 * DD);
    float4 rA1b = *(const float4*)(pA + (size_t)64 * DD + 4);
    load_b_stage(0, 0);
    asm volatile("cp.async.commit_group;" ::: "memory");
    load_b_stage(1, 32);
    asm volatile("cp.async.commit_group;" ::: "memory");
    // store A(0) into buf0
    cvt_store(sb + sA0, sb + sA0 + 8192, rA0a, rA0b);
    cvt_store(sb + sA1, sb + sA1 + 8192, rA1a, rA1b);
    // load A(1) into regs
    rA0a = *(const float4*)(pA + 32);
    rA0b = *(const float4*)(pA + 36);
    rA1a = *(const float4*)(pA + (size_t)64 * DD + 32);
    rA1b = *(const float4*)(pA + (size_t)64 * DD + 36);
    __syncthreads();

    for (int tile = 0; tile < 64; tile++) {
        if (tile + 2 < 64) load_b_stage((tile + 2) % 3, (tile + 2) * 32);
        asm volatile("cp.async.commit_group;" ::: "memory");
        asm volatile("cp.async.wait_group 2;" ::: "memory");

        const uint32_t abuf = sb + (uint32_t)(tile & 1) * HB_ABUF;
        const uint32_t bstg = sb + HB_BBASE + (uint32_t)(tile % 3) * HB_BSTG;
        mma_tile(fr, abuf, bstg, aAo, aBo);

        // store A(tile+1) from regs into the other buffer, then prefetch A(tile+2)
        if (tile + 1 < 64) {
            const uint32_t nbuf = sb + (uint32_t)((tile + 1) & 1) * HB_ABUF;
            cvt_store(nbuf + sA0, nbuf + sA0 + 8192, rA0a, rA0b);
            cvt_store(nbuf + sA1, nbuf + sA1 + 8192, rA1a, rA1b);
            if (tile + 2 < 64) {
                const float* p = pA + (size_t)(tile + 2) * 32;
                rA0a = *(const float4*)(p);
                rA0b = *(const float4*)(p + 4);
                rA1a = *(const float4*)(p + (size_t)64 * DD);
                rA1b = *(const float4*)(p + (size_t)64 * DD + 4);
            }
        }
        __syncthreads();
    }

    epilogue(fr, C, bias, m0, n0, wm, wn, lane);
}

// ============================================================================
// Scan chunk (R8 version — best measured): 64 blocks, one per (b, n),
// 128 threads, W in regs, state ping-pong in shared, y emitted as bf16 hi/lo.
// ============================================================================
__global__ __launch_bounds__(128, 1)
void scan_kernel(const float* __restrict__ x, const float* __restrict__ sin,
                 const float* __restrict__ SW,
                 __nv_bfloat16* __restrict__ yhi, __nv_bfloat16* __restrict__ ylo,
                 float* __restrict__ sfin, int s_base, int s_len) {
    const int b = blockIdx.x >> 4;
    const int n = blockIdx.x & 15;
    const int k = threadIdx.x;

    const float* Wn = SW + (size_t)n * HH * HH;
    ull w2[64];
    #pragma unroll
    for (int j = 0; j < 64; j++)
        w2[j] = pack2(Wn[(2 * j) * HH + k], Wn[(2 * j + 1) * HH + k]);

    __shared__ __align__(16) float sbuf[2][HH];
    sbuf[0][k] = sin[((size_t)b * NH + n) * HH + k];
    __syncthreads();

    const float* xp = x + ((size_t)b * SS + s_base) * DD + n * HH + k;
    __nv_bfloat16* yhp = yhi + ((size_t)b * SS + s_base) * DD + n * HH + k;
    __nv_bfloat16* ylp = ylo + ((size_t)b * SS + s_base) * DD + n * HH + k;

    float xa = xp[0];
    float xb = xp[DD];
    float xc = xp[2 * (size_t)DD];
    float v = 0.0f;

    for (int t = 0; t < s_len; t++) {
        float xn = 0.0f;
        if (t + 3 < s_len) xn = xp[(size_t)(t + 3) * DD];

        const ulonglong2* s4 = (const ulonglong2*)sbuf[t & 1];
        ull a0 = 0ull, a1 = 0ull, a2 = 0ull, a3 = 0ull;
        ull a4 = 0ull, a5 = 0ull, a6 = 0ull, a7 = 0ull;
        #pragma unroll
        for (int j = 0; j < 8; j++) {
            ulonglong2 p = s4[4 * j];
            ulonglong2 q = s4[4 * j + 1];
            ulonglong2 r = s4[4 * j + 2];
            ulonglong2 s = s4[4 * j + 3];
            a0 = ffma2(p.x, w2[8 * j + 0], a0);
            a1 = ffma2(p.y, w2[8 * j + 1], a1);
            a2 = ffma2(q.x, w2[8 * j + 2], a2);
            a3 = ffma2(q.y, w2[8 * j + 3], a3);
            a4 = ffma2(r.x, w2[8 * j + 4], a4);
            a5 = ffma2(r.y, w2[8 * j + 5], a5);
            a6 = ffma2(s.x, w2[8 * j + 6], a6);
            a7 = ffma2(s.y, w2[8 * j + 7], a7);
        }
        ull s01 = addf2(a0, a1), s23 = addf2(a2, a3);
        ull s45 = addf2(a4, a5), s67 = addf2(a6, a7);
        ull sall = addf2(addf2(s01, s23), addf2(s45, s67));
        float lo, hi;
        unpack2(sall, lo, hi);
        float dot = lo + hi;

        v = fast_tanh(dot + xa);
        __nv_bfloat16 h = __float2bfloat16(v);
        yhp[(size_t)t * DD] = h;
        ylp[(size_t)t * DD] = __float2bfloat16(v - __bfloat162float(h));
        sbuf[(t + 1) & 1][k] = v;

        xa = xb; xb = xc; xc = xn;
        __syncthreads();
    }

    sfin[((size_t)b * NH + n) * HH + k] = v;
}

// ============================================================================
// Launch: minimal prelude (weight splits only) + 3-stream chunked pipeline.
//   origin: gin_c x8 (hybrid: reads fp32 input directly)
//   st1 (hi prio): w_out split, then scan_c x8
//   st2: w_in split (gates gins), then gout_c x8
// ============================================================================
extern "C" void kernel_launch(void* const* d_in, const int* in_sizes, int n_in,
                              void* d_out, int out_size) {
    const float* input  = (const float*)d_in[0];
    const float* state0 = (const float*)d_in[1];
    const float* w_in   = (const float*)d_in[2];
    const float* b_in   = (const float*)d_in[3];
    const float* sw     = (const float*)d_in[4];
    const float* w_out  = (const float*)d_in[5];
    float* out = (float*)d_out;

    float *xbuf, *stbuf;
    __nv_bfloat16 *yhi, *ylo, *wihi, *wilo, *wohi, *wolo;
    cudaGetSymbolAddress((void**)&xbuf, g_x);
    cudaGetSymbolAddress((void**)&stbuf, g_state);
    cudaGetSymbolAddress((void**)&yhi, g_yhi);
    cudaGetSymbolAddress((void**)&ylo, g_ylo);
    cudaGetSymbolAddress((void**)&wihi, g_wihi);
    cudaGetSymbolAddress((void**)&wilo, g_wilo);
    cudaGetSymbolAddress((void**)&wohi, g_wohi);
    cudaGetSymbolAddress((void**)&wolo, g_wolo);

    static cudaStream_t st1 = nullptr, st2 = nullptr;
    static cudaEvent_t ev_gin[NCH], ev_scan[NCH], ev_root, ev_w, ev_tail;
    if (st1 == nullptr) {
        int prio_lo, prio_hi;
        cudaDeviceGetStreamPriorityRange(&prio_lo, &prio_hi);
        cudaStreamCreateWithPriority(&st1, cudaStreamNonBlocking, prio_hi);  // scan: highest
        cudaStreamCreateWithFlags(&st2, cudaStreamNonBlocking);
        for (int c = 0; c < NCH; c++) {
            cudaEventCreateWithFlags(&ev_gin[c], cudaEventDisableTiming);
            cudaEventCreateWithFlags(&ev_scan[c], cudaEventDisableTiming);
        }
        cudaEventCreateWithFlags(&ev_root, cudaEventDisableTiming);
        cudaEventCreateWithFlags(&ev_w, cudaEventDisableTiming);
        cudaEventCreateWithFlags(&ev_tail, cudaEventDisableTiming);
    }

    const int smem_gout = 3 * STAGE;                  // 98304
    const int smem_gin  = 2 * HB_ABUF + 3 * HB_BSTG;  // 81920
    cudaFuncSetAttribute(gemm_mma_kernel, cudaFuncAttributeMaxDynamicSharedMemorySize, smem_gout);
    cudaFuncSetAttribute(gemm_hybrid_kernel, cudaFuncAttributeMaxDynamicSharedMemorySize, smem_gin);

    // ---- prelude: w_in split on st2 (gates gins), w_out split on st1 (hidden) ----
    cudaEventRecord(ev_root, 0);
    cudaStreamWaitEvent(st1, ev_root, 0);
    cvt_split_kernel<<<4096, 256, 0, st1>>>(w_out, wohi, wolo, DD * DD / 4);
    cudaStreamWaitEvent(st2, ev_root, 0);
    cvt_split_kernel<<<4096, 256, 0, st2>>>(w_in, wihi, wilo, DD * DD / 4);
    cudaEventRecord(ev_w, st2);
    cudaStreamWaitEvent(0, ev_w, 0);

    dim3 ggrid(DD / 128, CH / 128, BB);  // (16, 4, 4) = 256 CTAs per chunk

    // Input-projection chunks (hybrid, reads fp32 input directly) on origin
    for (int c = 0; c < NCH; c++) {
        gemm_hybrid_kernel<<<ggrid, 256, smem_gin>>>(input, wihi, wilo, b_in, xbuf, c * CH);
        cudaEventRecord(ev_gin[c], 0);
    }

    // Scan chunks on high-priority stream (sequential by state dependency)
    for (int c = 0; c < NCH; c++) {
        cudaStreamWaitEvent(st1, ev_gin[c], 0);
        const float* s_init = (c == 0) ? state0 : stbuf;
        scan_kernel<<<BB * NH, HH, 0, st1>>>(xbuf, s_init, sw, yhi, ylo, stbuf, c * CH, CH);
        cudaEventRecord(ev_scan[c], st1);
    }

    // Output-projection chunks on st2
    for (int c = 0; c < NCH; c++) {
        cudaStreamWaitEvent(st2, ev_scan[c], 0);
        gemm_mma_kernel<<<ggrid, 256, smem_gout, st2>>>(yhi, ylo, wohi, wolo, nullptr, out, c * CH);
    }

    // Join forked work back to origin stream for graph capture
    cudaEventRecord(ev_tail, st2);
    cudaStreamWaitEvent(0, ev_tail, 0);
}

// round 16
// speedup vs baseline: 1.0786x; 1.0114x over previous
#include <cuda_runtime.h>
#include <cuda_bf16.h>
#include <math.h>
#include <stdint.h>

// Problem constants
#define BB 4
#define SS 4096
#define DD 2048
#define NH 16
#define HH 128
#define MTOT (BB * SS)   // 16384

// Chunked pipeline
#define NCH 8
#define CH  (SS / NCH)   // 512

typedef unsigned long long ull;

// ---- packed fp32x2 helpers ----
__device__ __forceinline__ ull ffma2(ull a, ull b, ull c) {
    ull d;
    asm("fma.rn.f32x2 %0, %1, %2, %3;" : "=l"(d) : "l"(a), "l"(b), "l"(c));
    return d;
}
__device__ __forceinline__ ull addf2(ull a, ull b) {
    ull d;
    asm("add.rn.f32x2 %0, %1, %2;" : "=l"(d) : "l"(a), "l"(b));
    return d;
}
__device__ __forceinline__ ull pack2(float lo, float hi) {
    ull r;
    asm("mov.b64 %0, {%1, %2};" : "=l"(r) : "f"(lo), "f"(hi));
    return r;
}
__device__ __forceinline__ void unpack2(ull v, float& lo, float& hi) {
    asm("mov.b64 {%0, %1}, %2;" : "=f"(lo), "=f"(hi) : "l"(v));
}
__device__ __forceinline__ uint32_t smem_u32(const void* p) {
    uint32_t a;
    asm("{ .reg .u64 t; cvta.to.shared.u64 t, %1; cvt.u32.u64 %0, t; }" : "=r"(a) : "l"(p));
    return a;
}

// fast tanh: (e^{2x}-1)/(e^{2x}+1) via MUFU ex2/rcp; rel err ~1e-7
__device__ __forceinline__ float fast_tanh(float x) {
    float t = fminf(x * 2.885390081777927f, 80.0f);
    float e;
    asm("ex2.approx.f32 %0, %1;" : "=f"(e) : "f"(t));
    float r;
    asm("rcp.approx.f32 %0, %1;" : "=f"(r) : "f"(e + 1.0f));
    return (e - 1.0f) * r;
}

// ---- mma.sync / ldmatrix / cp.async (plain PTX, assembles at compute_103) ----
__device__ __forceinline__ void ldsm4(uint32_t* r, uint32_t addr) {
    asm volatile("ldmatrix.sync.aligned.m8n8.x4.shared.b16 {%0,%1,%2,%3}, [%4];"
                 : "=r"(r[0]), "=r"(r[1]), "=r"(r[2]), "=r"(r[3]) : "r"(addr));
}
__device__ __forceinline__ void ldsm4t(uint32_t* r, uint32_t addr) {
    asm volatile("ldmatrix.sync.aligned.m8n8.x4.trans.shared.b16 {%0,%1,%2,%3}, [%4];"
                 : "=r"(r[0]), "=r"(r[1]), "=r"(r[2]), "=r"(r[3]) : "r"(addr));
}
__device__ __forceinline__ void mma_bf16(float* c, const uint32_t* a, uint32_t b0, uint32_t b1) {
    asm volatile("mma.sync.aligned.m16n8k16.row.col.f32.bf16.bf16.f32 "
                 "{%0,%1,%2,%3}, {%4,%5,%6,%7}, {%8,%9}, {%0,%1,%2,%3};"
                 : "+f"(c[0]), "+f"(c[1]), "+f"(c[2]), "+f"(c[3])
                 : "r"(a[0]), "r"(a[1]), "r"(a[2]), "r"(a[3]), "r"(b0), "r"(b1));
}
__device__ __forceinline__ void cp_async16(uint32_t saddr, const void* gaddr) {
    asm volatile("cp.async.cg.shared.global [%0], [%1], 16;"
                 :: "r"(saddr), "l"(gaddr) : "memory");
}

// ---- scratch (device globals; no allocation allowed) ----
__device__ float g_x[33554432];                               // (B,S,D) post-input-projection fp32
__device__ __nv_bfloat16 g_yhi[33554432],  g_ylo[33554432];   // scan output split
__device__ __nv_bfloat16 g_wihi[4194304],  g_wilo[4194304];   // w_in split
__device__ __nv_bfloat16 g_wohi[4194304],  g_wolo[4194304];   // w_out split
__device__ float g_state[BB * NH * HH];

// ============================================================================
// fp32 -> bf16 hi/lo split (weights only)
// ============================================================================
__global__ __launch_bounds__(256)
void cvt_split_kernel(const float* __restrict__ src,
                      __nv_bfloat16* __restrict__ hi,
                      __nv_bfloat16* __restrict__ lo, int n4) {
    int i = blockIdx.x * 256 + threadIdx.x;
    if (i >= n4) return;
    float4 v = ((const float4*)src)[i];
    float f[4] = {v.x, v.y, v.z, v.w};
    uint32_t hw[4], lw[4];
    #pragma unroll
    for (int j = 0; j < 4; j++) {
        __nv_bfloat16 h = __float2bfloat16(f[j]);
        float r = f[j] - __bfloat162float(h);
        __nv_bfloat16 l = __float2bfloat16(r);
        hw[j] = *(unsigned short*)&h;
        lw[j] = *(unsigned short*)&l;
    }
    *(uint2*)(hi + 4 * (size_t)i) = make_uint2(hw[0] | (hw[1] << 16), hw[2] | (hw[3] << 16));
    *(uint2*)(lo + 4 * (size_t)i) = make_uint2(lw[0] | (lw[1] << 16), lw[2] | (lw[3] << 16));
}

// ============================================================================
// Shared tiling helpers
// ============================================================================
__device__ __forceinline__ uint32_t aoff(int r, int c) {
    return (uint32_t)(r * 64 + ((c ^ ((r >> 1) & 3)) * 16));
}
__device__ __forceinline__ uint32_t boff(int kr, int c) {
    return (uint32_t)(kr * 256 + ((c ^ (kr & 7)) * 16));
}

// convert 8 fp32 -> 8 bf16 hi + 8 bf16 lo, store both to smem (16B each)
__device__ __forceinline__ void cvt_store(uint32_t dhi, uint32_t dlo, float4 v0, float4 v1) {
    float f[8] = {v0.x, v0.y, v0.z, v0.w, v1.x, v1.y, v1.z, v1.w};
    uint32_t h[4], l[4];
    #pragma unroll
    for (int p = 0; p < 4; p++) {
        uint32_t hp;
        asm("cvt.rn.bf16x2.f32 %0, %1, %2;" : "=r"(hp) : "f"(f[2 * p + 1]), "f"(f[2 * p]));
        float h0 = __uint_as_float(hp << 16);
        float h1 = __uint_as_float(hp & 0xFFFF0000u);
        float l0 = f[2 * p] - h0;
        float l1 = f[2 * p + 1] - h1;
        uint32_t lp;
        asm("cvt.rn.bf16x2.f32 %0, %1, %2;" : "=r"(lp) : "f"(l1), "f"(l0));
        h[p] = hp; l[p] = lp;
    }
    asm volatile("st.shared.v4.b32 [%0], {%1,%2,%3,%4};"
                 :: "r"(dhi), "r"(h[0]), "r"(h[1]), "r"(h[2]), "r"(h[3]));
    asm volatile("st.shared.v4.b32 [%0], {%1,%2,%3,%4};"
                 :: "r"(dlo), "r"(l[0]), "r"(l[1]), "r"(l[2]), "r"(l[3]));
}

// Shared MMA core: 3-pass (ahi*bhi + alo*bhi + ahi*blo) for one BK=32 tile.
struct Frag { float acc[2][8][4]; };

__device__ __forceinline__ void mma_tile(Frag& fr, uint32_t abase, uint32_t bbase,
                                         const uint32_t aAo[2][2], const uint32_t aBo[2][4]) {
    #pragma unroll
    for (int ks = 0; ks < 2; ks++) {
        uint32_t ah[2][4], al[2][4], bx[4][4];
        ldsm4(ah[0], abase + aAo[0][ks]);
        ldsm4(ah[1], abase + aAo[1][ks]);
        ldsm4(al[0], abase + aAo[0][ks] + 8192);
        ldsm4(al[1], abase + aAo[1][ks] + 8192);
        #pragma unroll
        for (int bq = 0; bq < 4; bq++) ldsm4t(bx[bq], bbase + aBo[ks][bq]);

        #pragma unroll
        for (int mt = 0; mt < 2; mt++)
            #pragma unroll
            for (int nt = 0; nt < 8; nt++) {
                const int bq = nt >> 1, of = (nt & 1) * 2;
                mma_bf16(fr.acc[mt][nt], ah[mt], bx[bq][of], bx[bq][of + 1]);
            }
        #pragma unroll
        for (int mt = 0; mt < 2; mt++)
            #pragma unroll
            for (int nt = 0; nt < 8; nt++) {
                const int bq = nt >> 1, of = (nt & 1) * 2;
                mma_bf16(fr.acc[mt][nt], al[mt], bx[bq][of], bx[bq][of + 1]);
            }
        #pragma unroll
        for (int bq = 0; bq < 4; bq++) ldsm4t(bx[bq], bbase + aBo[ks][bq] + 8192);
        #pragma unroll
        for (int mt = 0; mt < 2; mt++)
            #pragma unroll
            for (int nt = 0; nt < 8; nt++) {
                const int bq = nt >> 1, of = (nt & 1) * 2;
                mma_bf16(fr.acc[mt][nt], ah[mt], bx[bq][of], bx[bq][of + 1]);
            }
    }
}

__device__ __forceinline__ void epilogue(const Frag& fr, float* C, const float* bias,
                                         size_t m0, size_t n0, int wm, int wn, int lane) {
    const int g  = lane >> 2;
    const int tc = lane & 3;
    #pragma unroll
    for (int mt = 0; mt < 2; mt++) {
        const size_t row0 = m0 + wm * 32 + mt * 16 + g;
        #pragma unroll
        for (int nt = 0; nt < 8; nt++) {
            const size_t col = n0 + wn * 64 + nt * 8 + tc * 2;
            float b0 = 0.0f, b1 = 0.0f;
            if (bias != nullptr) { b0 = bias[col]; b1 = bias[col + 1]; }
            float2 v0 = make_float2(fr.acc[mt][nt][0] + b0, fr.acc[mt][nt][1] + b1);
            float2 v1 = make_float2(fr.acc[mt][nt][2] + b0, fr.acc[mt][nt][3] + b1);
            *(float2*)(C + row0 * DD + col)       = v0;
            *(float2*)(C + (row0 + 8) * DD + col) = v1;
        }
    }
}

// ============================================================================
// gout GEMM: pre-split bf16 operands, 3-stage cp.async, 96KB, 2 CTAs/SM.
// Single-barrier-per-tile loop: wait_group 1 -> sync -> load(t+2) -> commit -> mma.
// ============================================================================
#define STAGE 32768

__global__ __launch_bounds__(256, 2)
void gemm_mma_kernel(const __nv_bfloat16* __restrict__ Ahi, const __nv_bfloat16* __restrict__ Alo,
                     const __nv_bfloat16* __restrict__ Bhi, const __nv_bfloat16* __restrict__ Blo,
                     const float* __restrict__ bias, float* __restrict__ C, int s_base) {
    extern __shared__ __align__(128) char smem[];
    const uint32_t sb = smem_u32(smem);

    const int t    = threadIdx.x;
    const int lane = t & 31;
    const int wid  = t >> 5;
    const int wm   = wid >> 1;
    const int wn   = wid & 1;
    const size_t m0 = (size_t)blockIdx.z * SS + (size_t)s_base + (size_t)blockIdx.y * 128;
    const size_t n0 = (size_t)blockIdx.x * 128;

    const int ar = t >> 2, ac = t & 3;
    const int br = t >> 4, bc = t & 15;
    const __nv_bfloat16* pAh = Ahi + (m0 + ar) * DD + ac * 8;
    const __nv_bfloat16* pAl = Alo + (m0 + ar) * DD + ac * 8;
    const __nv_bfloat16* pBh = Bhi + (size_t)br * DD + n0 + bc * 8;
    const __nv_bfloat16* pBl = Blo + (size_t)br * DD + n0 + bc * 8;
    const uint32_t sA0 = aoff(ar, ac);
    const uint32_t sA1 = aoff(ar + 64, ac);
    const uint32_t sB0 = 16384 + boff(br, bc);
    const uint32_t sB1 = 16384 + boff(br + 16, bc);

    const int arow = wm * 32 + (lane & 7) + ((lane >> 3) & 1) * 8;
    const int akh  = (lane >> 4) & 1;
    uint32_t aAo[2][2];
    #pragma unroll
    for (int mt = 0; mt < 2; mt++)
        #pragma unroll
        for (int ks = 0; ks < 2; ks++)
            aAo[mt][ks] = aoff(arow + mt * 16, ks * 2 + akh);
    const int bpair = lane >> 4;
    const int bkr0  = ((lane >> 3) & 1) * 8 + (lane & 7);
    uint32_t aBo[2][4];
    #pragma unroll
    for (int ks = 0; ks < 2; ks++)
        #pragma unroll
        for (int bq = 0; bq < 4; bq++)
            aBo[ks][bq] = boff(ks * 16 + bkr0, wn * 8 + bq * 2 + bpair);

    Frag fr;
    #pragma unroll
    for (int mt = 0; mt < 2; mt++)
        #pragma unroll
        for (int nt = 0; nt < 8; nt++)
            #pragma unroll
            for (int i = 0; i < 4; i++) fr.acc[mt][nt][i] = 0.0f;

    auto load_stage = [&](int stg, int k0) {
        const uint32_t s = sb + (uint32_t)stg * STAGE;
        cp_async16(s + sA0, pAh + k0);
        cp_async16(s + sA1, pAh + (size_t)64 * DD + k0);
        cp_async16(s + sA0 + 8192, pAl + k0);
        cp_async16(s + sA1 + 8192, pAl + (size_t)64 * DD + k0);
        cp_async16(s + sB0, pBh + (size_t)k0 * DD);
        cp_async16(s + sB1, pBh + (size_t)(k0 + 16) * DD);
        cp_async16(s + sB0 + 8192, pBl + (size_t)k0 * DD);
        cp_async16(s + sB1 + 8192, pBl + (size_t)(k0 + 16) * DD);
    };

    load_stage(0, 0);
    asm volatile("cp.async.commit_group;" ::: "memory");
    load_stage(1, 32);
    asm volatile("cp.async.commit_group;" ::: "memory");

    for (int tile = 0; tile < 64; tile++) {
        asm volatile("cp.async.wait_group 1;" ::: "memory");   // tile's group done
        __syncthreads();                                        // visible + prior reads done
        if (tile + 2 < 64) load_stage((tile + 2) % 3, (tile + 2) * 32);
        asm volatile("cp.async.commit_group;" ::: "memory");    // (empty on tail iters)

        const uint32_t stg = sb + (uint32_t)(tile % 3) * STAGE;
        mma_tile(fr, stg, stg + 16384, aAo, aBo);
    }

    epilogue(fr, C, bias, m0, n0, wm, wn, lane);
}

// ============================================================================
// gin hybrid GEMM: A = raw fp32 input (LDG -> hi/lo cvt -> STS, double-buffered),
// B = pre-split bf16 weights via 3-stage cp.async. Single barrier per tile.
// smem: A 2x16KB @ {0,16K}; B 3x16KB @ {32K,48K,64K} = 80KB, 2 CTAs/SM.
// ============================================================================
#define HB_ABUF 16384
#define HB_BBASE 32768
#define HB_BSTG 16384

__global__ __launch_bounds__(256, 2)
void gemm_hybrid_kernel(const float* __restrict__ A,
                        const __nv_bfloat16* __restrict__ Bhi, const __nv_bfloat16* __restrict__ Blo,
                        const float* __restrict__ bias, float* __restrict__ C, int s_base) {
    extern __shared__ __align__(128) char smem[];
    const uint32_t sb = smem_u32(smem);

    const int t    = threadIdx.x;
    const int lane = t & 31;
    const int wid  = t >> 5;
    const int wm   = wid >> 1;
    const int wn   = wid & 1;
    const size_t m0 = (size_t)blockIdx.z * SS + (size_t)s_base + (size_t)blockIdx.y * 128;
    const size_t n0 = (size_t)blockIdx.x * 128;

    const int ar = t >> 2, ac = t & 3;
    const int br = t >> 4, bc = t & 15;
    const float* pA = A + (m0 + ar) * DD + ac * 8;   // fp32
    const __nv_bfloat16* pBh = Bhi + (size_t)br * DD + n0 + bc * 8;
    const __nv_bfloat16* pBl = Blo + (size_t)br * DD + n0 + bc * 8;
    const uint32_t sA0 = aoff(ar, ac);
    const uint32_t sA1 = aoff(ar + 64, ac);
    const uint32_t sB0 = HB_BBASE + boff(br, bc);
    const uint32_t sB1 = HB_BBASE + boff(br + 16, bc);

    const int arow = wm * 32 + (lane & 7) + ((lane >> 3) & 1) * 8;
    const int akh  = (lane >> 4) & 1;
    uint32_t aAo[2][2];
    #pragma unroll
    for (int mt = 0; mt < 2; mt++)
        #pragma unroll
        for (int ks = 0; ks < 2; ks++)
            aAo[mt][ks] = aoff(arow + mt * 16, ks * 2 + akh);
    const int bpair = lane >> 4;
    const int bkr0  = ((lane >> 3) & 1) * 8 + (lane & 7);
    uint32_t aBo[2][4];
    #pragma unroll
    for (int ks = 0; ks < 2; ks++)
        #pragma unroll
        for (int bq = 0; bq < 4; bq++)
            aBo[ks][bq] = boff(ks * 16 + bkr0, wn * 8 + bq * 2 + bpair);

    Frag fr;
    #pragma unroll
    for (int mt = 0; mt < 2; mt++)
        #pragma unroll
        for (int nt = 0; nt < 8; nt++)
            #pragma unroll
            for (int i = 0; i < 4; i++) fr.acc[mt][nt][i] = 0.0f;

    auto load_b_stage = [&](int stg, int k0) {
        const uint32_t off = (uint32_t)stg * HB_BSTG;
        cp_async16(sb + sB0 + off, pBh + (size_t)k0 * DD);
        cp_async16(sb + sB1 + off, pBh + (size_t)(k0 + 16) * DD);
        cp_async16(sb + sB0 + off + 8192, pBl + (size_t)k0 * DD);
        cp_async16(sb + sB1 + off + 8192, pBl + (size_t)(k0 + 16) * DD);
    };

    // ---- prologue ----
    float4 rA0a = *(const float4*)(pA);
    float4 rA0b = *(const float4*)(pA + 4);
    float4 rA1a = *(const float4*)(pA + (size_t)64 * DD);
    float4 rA1b = *(const float4*)(pA + (size_t)64 * DD + 4);
    load_b_stage(0, 0);
    asm volatile("cp.async.commit_group;" ::: "memory");
    load_b_stage(1, 32);
    asm volatile("cp.async.commit_group;" ::: "memory");
    // store A(0) into buf0
    cvt_store(sb + sA0, sb + sA0 + 8192, rA0a, rA0b);
    cvt_store(sb + sA1, sb + sA1 + 8192, rA1a, rA1b);
    // load A(1) into regs
    rA0a = *(const float4*)(pA + 32);
    rA0b = *(const float4*)(pA + 36);
    rA1a = *(const float4*)(pA + (size_t)64 * DD + 32);
    rA1b = *(const float4*)(pA + (size_t)64 * DD + 36);

    for (int tile = 0; tile < 64; tile++) {
        asm volatile("cp.async.wait_group 1;" ::: "memory");
        __syncthreads();
        if (tile + 2 < 64) load_b_stage((tile + 2) % 3, (tile + 2) * 32);
        asm volatile("cp.async.commit_group;" ::: "memory");

        const uint32_t abuf = sb + (uint32_t)(tile & 1) * HB_ABUF;
        const uint32_t bstg = sb + HB_BBASE + (uint32_t)(tile % 3) * HB_BSTG;
        mma_tile(fr, abuf, bstg, aAo, aBo);

        // store A(tile+1) into other buffer (readers of it finished pre-sync),
        // then prefetch A(tile+2) into regs
        if (tile + 1 < 64) {
            const uint32_t nbuf = sb + (uint32_t)((tile + 1) & 1) * HB_ABUF;
            cvt_store(nbuf + sA0, nbuf + sA0 + 8192, rA0a, rA0b);
            cvt_store(nbuf + sA1, nbuf + sA1 + 8192, rA1a, rA1b);
            if (tile + 2 < 64) {
                const float* p = pA + (size_t)(tile + 2) * 32;
                rA0a = *(const float4*)(p);
                rA0b = *(const float4*)(p + 4);
                rA1a = *(const float4*)(p + (size_t)64 * DD);
                rA1b = *(const float4*)(p + (size_t)64 * DD + 4);
            }
        }
    }

    epilogue(fr, C, bias, m0, n0, wm, wn, lane);
}

// ============================================================================
// Scan chunk v3: TWO independent heads per CTA (256 thr; head = tid>>7).
// 2 warps/SMSP interleave to hide LDS/FFMA/MUFU latency; ONE barrier per step
// shared by both heads. 32 blocks = (b, head-pair).
// ============================================================================
__global__ __launch_bounds__(256, 1)
void scan_kernel(const float* __restrict__ x, const float* __restrict__ sin,
                 const float* __restrict__ SW,
                 __nv_bfloat16* __restrict__ yhi, __nv_bfloat16* __restrict__ ylo,
                 float* __restrict__ sfin, int s_base, int s_len) {
    const int b    = blockIdx.x >> 3;
    const int np   = blockIdx.x & 7;
    const int head = threadIdx.x >> 7;
    const int k    = threadIdx.x & 127;
    const int n    = np * 2 + head;

    const float* Wn = SW + (size_t)n * HH * HH;
    ull w2[64];
    #pragma unroll
    for (int j = 0; j < 64; j++)
        w2[j] = pack2(Wn[(2 * j) * HH + k], Wn[(2 * j + 1) * HH + k]);

    __shared__ __align__(16) float sbuf[2][2][HH];   // [buf][head][k]
    sbuf[0][head][k] = sin[((size_t)b * NH + n) * HH + k];
    __syncthreads();

    const float* xp = x + ((size_t)b * SS + s_base) * DD + n * HH + k;
    __nv_bfloat16* yhp = yhi + ((size_t)b * SS + s_base) * DD + n * HH + k;
    __nv_bfloat16* ylp = ylo + ((size_t)b * SS + s_base) * DD + n * HH + k;

    float xa = xp[0];
    float xb = xp[DD];
    float xc = xp[2 * (size_t)DD];
    float v = 0.0f;

    for (int t = 0; t < s_len; t++) {
        float xn = 0.0f;
        if (t + 3 < s_len) xn = xp[(size_t)(t + 3) * DD];

        const ulonglong2* s4 = (const ulonglong2*)sbuf[t & 1][head];
        ull a0 = 0ull, a1 = 0ull, a2 = 0ull, a3 = 0ull;
        ull a4 = 0ull, a5 = 0ull, a6 = 0ull, a7 = 0ull;
        #pragma unroll
        for (int j = 0; j < 8; j++) {
            ulonglong2 p = s4[4 * j];
            ulonglong2 q = s4[4 * j + 1];
            ulonglong2 r = s4[4 * j + 2];
            ulonglong2 s = s4[4 * j + 3];
            a0 = ffma2(p.x, w2[8 * j + 0], a0);
            a1 = ffma2(p.y, w2[8 * j + 1], a1);
            a2 = ffma2(q.x, w2[8 * j + 2], a2);
            a3 = ffma2(q.y, w2[8 * j + 3], a3);
            a4 = ffma2(r.x, w2[8 * j + 4], a4);
            a5 = ffma2(r.y, w2[8 * j + 5], a5);
            a6 = ffma2(s.x, w2[8 * j + 6], a6);
            a7 = ffma2(s.y, w2[8 * j + 7], a7);
        }
        ull s01 = addf2(a0, a1), s23 = addf2(a2, a3);
        ull s45 = addf2(a4, a5), s67 = addf2(a6, a7);
        ull sall = addf2(addf2(s01, s23), addf2(s45, s67));
        float lo, hi;
        unpack2(sall, lo, hi);
        float dot = lo + hi;

        v = fast_tanh(dot + xa);
        __nv_bfloat16 h = __float2bfloat16(v);
        yhp[(size_t)t * DD] = h;
        ylp[(size_t)t * DD] = __float2bfloat16(v - __bfloat162float(h));
        sbuf[(t + 1) & 1][head][k] = v;

        xa = xb; xb = xc; xc = xn;
        __syncthreads();
    }

    sfin[((size_t)b * NH + n) * HH + k] = v;
}

// ============================================================================
// Launch: minimal prelude (weight splits only) + 3-stream chunked pipeline.
//   origin: gin_c x8 (hybrid)    st1 (hi prio): w_out split + scan_c x8
//   st2: w_in split + gout_c x8
// ============================================================================
extern "C" void kernel_launch(void* const* d_in, const int* in_sizes, int n_in,
                              void* d_out, int out_size) {
    const float* input  = (const float*)d_in[0];
    const float* state0 = (const float*)d_in[1];
    const float* w_in   = (const float*)d_in[2];
    const float* b_in   = (const float*)d_in[3];
    const float* sw     = (const float*)d_in[4];
    const float* w_out  = (const float*)d_in[5];
    float* out = (float*)d_out;

    float *xbuf, *stbuf;
    __nv_bfloat16 *yhi, *ylo, *wihi, *wilo, *wohi, *wolo;
    cudaGetSymbolAddress((void**)&xbuf, g_x);
    cudaGetSymbolAddress((void**)&stbuf, g_state);
    cudaGetSymbolAddress((void**)&yhi, g_yhi);
    cudaGetSymbolAddress((void**)&ylo, g_ylo);
    cudaGetSymbolAddress((void**)&wihi, g_wihi);
    cudaGetSymbolAddress((void**)&wilo, g_wilo);
    cudaGetSymbolAddress((void**)&wohi, g_wohi);
    cudaGetSymbolAddress((void**)&wolo, g_wolo);

    static cudaStream_t st1 = nullptr, st2 = nullptr;
    static cudaEvent_t ev_gin[NCH], ev_scan[NCH], ev_root, ev_w, ev_tail;
    if (st1 == nullptr) {
        int prio_lo, prio_hi;
        cudaDeviceGetStreamPriorityRange(&prio_lo, &prio_hi);
        cudaStreamCreateWithPriority(&st1, cudaStreamNonBlocking, prio_hi);  // scan: highest
        cudaStreamCreateWithFlags(&st2, cudaStreamNonBlocking);
        for (int c = 0; c < NCH; c++) {
            cudaEventCreateWithFlags(&ev_gin[c], cudaEventDisableTiming);
            cudaEventCreateWithFlags(&ev_scan[c], cudaEventDisableTiming);
        }
        cudaEventCreateWithFlags(&ev_root, cudaEventDisableTiming);
        cudaEventCreateWithFlags(&ev_w, cudaEventDisableTiming);
        cudaEventCreateWithFlags(&ev_tail, cudaEventDisableTiming);
    }

    const int smem_gout = 3 * STAGE;                  // 98304
    const int smem_gin  = 2 * HB_ABUF + 3 * HB_BSTG;  // 81920
    cudaFuncSetAttribute(gemm_mma_kernel, cudaFuncAttributeMaxDynamicSharedMemorySize, smem_gout);
    cudaFuncSetAttribute(gemm_hybrid_kernel, cudaFuncAttributeMaxDynamicSharedMemorySize, smem_gin);

    // ---- prelude: w_out split on st1 (hidden), w_in split on st2 (gates gins) ----
    cudaEventRecord(ev_root, 0);
    cudaStreamWaitEvent(st1, ev_root, 0);
    cvt_split_kernel<<<4096, 256, 0, st1>>>(w_out, wohi, wolo, DD * DD / 4);
    cudaStreamWaitEvent(st2, ev_root, 0);
    cvt_split_kernel<<<4096, 256, 0, st2>>>(w_in, wihi, wilo, DD * DD / 4);
    cudaEventRecord(ev_w, st2);
    cudaStreamWaitEvent(0, ev_w, 0);

    dim3 ggrid(DD / 128, CH / 128, BB);  // (16, 4, 4) = 256 CTAs per chunk

    // Input-projection chunks (hybrid, reads fp32 input directly) on origin
    for (int c = 0; c < NCH; c++) {
        gemm_hybrid_kernel<<<ggrid, 256, smem_gin>>>(input, wihi, wilo, b_in, xbuf, c * CH);
        cudaEventRecord(ev_gin[c], 0);
    }

    // Scan chunks on high-priority stream (sequential by state dependency)
    for (int c = 0; c < NCH; c++) {
        cudaStreamWaitEvent(st1, ev_gin[c], 0);
        const float* s_init = (c == 0) ? state0 : stbuf;
        scan_kernel<<<BB * NH / 2, 256, 0, st1>>>(xbuf, s_init, sw, yhi, ylo, stbuf, c * CH, CH);
        cudaEventRecord(ev_scan[c], st1);
    }

    // Output-projection chunks on st2
    for (int c = 0; c < NCH; c++) {
        cudaStreamWaitEvent(st2, ev_scan[c], 0);
        gemm_mma_kernel<<<ggrid, 256, smem_gout, st2>>>(yhi, ylo, wohi, wolo, nullptr, out, c * CH);
    }

    // Join forked work back to origin stream for graph capture
    cudaEventRecord(ev_tail, st2);
    cudaStreamWaitEvent(0, ev_tail, 0);
}

// round 17
// speedup vs baseline: 1.0857x; 1.0066x over previous
#include <cuda_runtime.h>
#include <cuda_bf16.h>
#include <cuda_fp16.h>
#include <math.h>
#include <stdint.h>

// Problem constants
#define BB 4
#define SS 4096
#define DD 2048
#define NH 16
#define HH 128
#define MTOT (BB * SS)   // 16384

// Chunked pipeline
#define NCH 8
#define CH  (SS / NCH)   // 512

typedef unsigned long long ull;

// ---- packed fp32x2 helpers ----
__device__ __forceinline__ ull ffma2(ull a, ull b, ull c) {
    ull d;
    asm("fma.rn.f32x2 %0, %1, %2, %3;" : "=l"(d) : "l"(a), "l"(b), "l"(c));
    return d;
}
__device__ __forceinline__ ull addf2(ull a, ull b) {
    ull d;
    asm("add.rn.f32x2 %0, %1, %2;" : "=l"(d) : "l"(a), "l"(b));
    return d;
}
__device__ __forceinline__ ull pack2(float lo, float hi) {
    ull r;
    asm("mov.b64 %0, {%1, %2};" : "=l"(r) : "f"(lo), "f"(hi));
    return r;
}
__device__ __forceinline__ void unpack2(ull v, float& lo, float& hi) {
    asm("mov.b64 {%0, %1}, %2;" : "=f"(lo), "=f"(hi) : "l"(v));
}
__device__ __forceinline__ uint32_t smem_u32(const void* p) {
    uint32_t a;
    asm("{ .reg .u64 t; cvta.to.shared.u64 t, %1; cvt.u32.u64 %0, t; }" : "=r"(a) : "l"(p));
    return a;
}

// fast tanh: (e^{2x}-1)/(e^{2x}+1) via MUFU ex2/rcp; rel err ~1e-7
__device__ __forceinline__ float fast_tanh(float x) {
    float t = fminf(x * 2.885390081777927f, 80.0f);
    float e;
    asm("ex2.approx.f32 %0, %1;" : "=f"(e) : "f"(t));
    float r;
    asm("rcp.approx.f32 %0, %1;" : "=f"(r) : "f"(e + 1.0f));
    return (e - 1.0f) * r;
}

// ---- mma.sync / ldmatrix / cp.async (plain PTX, assembles at compute_103) ----
__device__ __forceinline__ void ldsm4(uint32_t* r, uint32_t addr) {
    asm volatile("ldmatrix.sync.aligned.m8n8.x4.shared.b16 {%0,%1,%2,%3}, [%4];"
                 : "=r"(r[0]), "=r"(r[1]), "=r"(r[2]), "=r"(r[3]) : "r"(addr));
}
__device__ __forceinline__ void ldsm4t(uint32_t* r, uint32_t addr) {
    asm volatile("ldmatrix.sync.aligned.m8n8.x4.trans.shared.b16 {%0,%1,%2,%3}, [%4];"
                 : "=r"(r[0]), "=r"(r[1]), "=r"(r[2]), "=r"(r[3]) : "r"(addr));
}
__device__ __forceinline__ void mma_bf16(float* c, const uint32_t* a, uint32_t b0, uint32_t b1) {
    asm volatile("mma.sync.aligned.m16n8k16.row.col.f32.bf16.bf16.f32 "
                 "{%0,%1,%2,%3}, {%4,%5,%6,%7}, {%8,%9}, {%0,%1,%2,%3};"
                 : "+f"(c[0]), "+f"(c[1]), "+f"(c[2]), "+f"(c[3])
                 : "r"(a[0]), "r"(a[1]), "r"(a[2]), "r"(a[3]), "r"(b0), "r"(b1));
}
__device__ __forceinline__ void mma_f16(float* c, const uint32_t* a, uint32_t b0, uint32_t b1) {
    asm volatile("mma.sync.aligned.m16n8k16.row.col.f32.f16.f16.f32 "
                 "{%0,%1,%2,%3}, {%4,%5,%6,%7}, {%8,%9}, {%0,%1,%2,%3};"
                 : "+f"(c[0]), "+f"(c[1]), "+f"(c[2]), "+f"(c[3])
                 : "r"(a[0]), "r"(a[1]), "r"(a[2]), "r"(a[3]), "r"(b0), "r"(b1));
}
__device__ __forceinline__ void cp_async16(uint32_t saddr, const void* gaddr) {
    asm volatile("cp.async.cg.shared.global [%0], [%1], 16;"
                 :: "r"(saddr), "l"(gaddr) : "memory");
}

// ---- scratch (device globals; no allocation allowed) ----
__device__ float g_x[33554432];                               // (B,S,D) post-input-projection fp32
__device__ __half g_yhi[33554432], g_ylo[33554432];           // scan output split (fp16)
__device__ __nv_bfloat16 g_wihi[4194304], g_wilo[4194304];    // w_in split (bf16, 3-pass gin)
__device__ __half g_woh[4194304];                             // w_out fp16 (2-pass gout)
__device__ float g_state[BB * NH * HH];

// ============================================================================
// weight conversion kernels
// ============================================================================
__global__ __launch_bounds__(256)
void cvt_split_kernel(const float* __restrict__ src,
                      __nv_bfloat16* __restrict__ hi,
                      __nv_bfloat16* __restrict__ lo, int n4) {
    int i = blockIdx.x * 256 + threadIdx.x;
    if (i >= n4) return;
    float4 v = ((const float4*)src)[i];
    float f[4] = {v.x, v.y, v.z, v.w};
    uint32_t hw[4], lw[4];
    #pragma unroll
    for (int j = 0; j < 4; j++) {
        __nv_bfloat16 h = __float2bfloat16(f[j]);
        float r = f[j] - __bfloat162float(h);
        __nv_bfloat16 l = __float2bfloat16(r);
        hw[j] = *(unsigned short*)&h;
        lw[j] = *(unsigned short*)&l;
    }
    *(uint2*)(hi + 4 * (size_t)i) = make_uint2(hw[0] | (hw[1] << 16), hw[2] | (hw[3] << 16));
    *(uint2*)(lo + 4 * (size_t)i) = make_uint2(lw[0] | (lw[1] << 16), lw[2] | (lw[3] << 16));
}

__global__ __launch_bounds__(256)
void cvt_f16_kernel(const float* __restrict__ src, __half* __restrict__ dst, int n4) {
    int i = blockIdx.x * 256 + threadIdx.x;
    if (i >= n4) return;
    float4 v = ((const float4*)src)[i];
    uint32_t p0, p1;
    asm("cvt.rn.f16x2.f32 %0, %1, %2;" : "=r"(p0) : "f"(v.y), "f"(v.x));
    asm("cvt.rn.f16x2.f32 %0, %1, %2;" : "=r"(p1) : "f"(v.w), "f"(v.z));
    *(uint2*)(dst + 4 * (size_t)i) = make_uint2(p0, p1);
}

// ============================================================================
// Shared tiling helpers
// ============================================================================
__device__ __forceinline__ uint32_t aoff(int r, int c) {
    return (uint32_t)(r * 64 + ((c ^ ((r >> 1) & 3)) * 16));
}
__device__ __forceinline__ uint32_t boff(int kr, int c) {
    return (uint32_t)(kr * 256 + ((c ^ (kr & 7)) * 16));
}

// convert 8 fp32 -> 8 bf16 hi + 8 bf16 lo, store both to smem (16B each)
__device__ __forceinline__ void cvt_store(uint32_t dhi, uint32_t dlo, float4 v0, float4 v1) {
    float f[8] = {v0.x, v0.y, v0.z, v0.w, v1.x, v1.y, v1.z, v1.w};
    uint32_t h[4], l[4];
    #pragma unroll
    for (int p = 0; p < 4; p++) {
        uint32_t hp;
        asm("cvt.rn.bf16x2.f32 %0, %1, %2;" : "=r"(hp) : "f"(f[2 * p + 1]), "f"(f[2 * p]));
        float h0 = __uint_as_float(hp << 16);
        float h1 = __uint_as_float(hp & 0xFFFF0000u);
        float l0 = f[2 * p] - h0;
        float l1 = f[2 * p + 1] - h1;
        uint32_t lp;
        asm("cvt.rn.bf16x2.f32 %0, %1, %2;" : "=r"(lp) : "f"(l1), "f"(l0));
        h[p] = hp; l[p] = lp;
    }
    asm volatile("st.shared.v4.b32 [%0], {%1,%2,%3,%4};"
                 :: "r"(dhi), "r"(h[0]), "r"(h[1]), "r"(h[2]), "r"(h[3]));
    asm volatile("st.shared.v4.b32 [%0], {%1,%2,%3,%4};"
                 :: "r"(dlo), "r"(l[0]), "r"(l[1]), "r"(l[2]), "r"(l[3]));
}

struct Frag { float acc[2][8][4]; };

// 3-pass bf16 MMA core (gin): ahi*bhi + alo*bhi + ahi*blo
__device__ __forceinline__ void mma_tile(Frag& fr, uint32_t abase, uint32_t bbase,
                                         const uint32_t aAo[2][2], const uint32_t aBo[2][4]) {
    #pragma unroll
    for (int ks = 0; ks < 2; ks++) {
        uint32_t ah[2][4], al[2][4], bx[4][4];
        ldsm4(ah[0], abase + aAo[0][ks]);
        ldsm4(ah[1], abase + aAo[1][ks]);
        ldsm4(al[0], abase + aAo[0][ks] + 8192);
        ldsm4(al[1], abase + aAo[1][ks] + 8192);
        #pragma unroll
        for (int bq = 0; bq < 4; bq++) ldsm4t(bx[bq], bbase + aBo[ks][bq]);

        #pragma unroll
        for (int mt = 0; mt < 2; mt++)
            #pragma unroll
            for (int nt = 0; nt < 8; nt++) {
                const int bq = nt >> 1, of = (nt & 1) * 2;
                mma_bf16(fr.acc[mt][nt], ah[mt], bx[bq][of], bx[bq][of + 1]);
            }
        #pragma unroll
        for (int mt = 0; mt < 2; mt++)
            #pragma unroll
            for (int nt = 0; nt < 8; nt++) {
                const int bq = nt >> 1, of = (nt & 1) * 2;
                mma_bf16(fr.acc[mt][nt], al[mt], bx[bq][of], bx[bq][of + 1]);
            }
        #pragma unroll
        for (int bq = 0; bq < 4; bq++) ldsm4t(bx[bq], bbase + aBo[ks][bq] + 8192);
        #pragma unroll
        for (int mt = 0; mt < 2; mt++)
            #pragma unroll
            for (int nt = 0; nt < 8; nt++) {
                const int bq = nt >> 1, of = (nt & 1) * 2;
                mma_bf16(fr.acc[mt][nt], ah[mt], bx[bq][of], bx[bq][of + 1]);
            }
    }
}

// 2-pass fp16 MMA core (gout): (ahi + alo) * bhi  — error = b's fp16 rounding
__device__ __forceinline__ void mma_tile_f16(Frag& fr, uint32_t abase, uint32_t bbase,
                                             const uint32_t aAo[2][2], const uint32_t aBo[2][4]) {
    #pragma unroll
    for (int ks = 0; ks < 2; ks++) {
        uint32_t ah[2][4], al[2][4], bx[4][4];
        ldsm4(ah[0], abase + aAo[0][ks]);
        ldsm4(ah[1], abase + aAo[1][ks]);
        ldsm4(al[0], abase + aAo[0][ks] + 8192);
        ldsm4(al[1], abase + aAo[1][ks] + 8192);
        #pragma unroll
        for (int bq = 0; bq < 4; bq++) ldsm4t(bx[bq], bbase + aBo[ks][bq]);

        #pragma unroll
        for (int mt = 0; mt < 2; mt++)
            #pragma unroll
            for (int nt = 0; nt < 8; nt++) {
                const int bq = nt >> 1, of = (nt & 1) * 2;
                mma_f16(fr.acc[mt][nt], ah[mt], bx[bq][of], bx[bq][of + 1]);
            }
        #pragma unroll
        for (int mt = 0; mt < 2; mt++)
            #pragma unroll
            for (int nt = 0; nt < 8; nt++) {
                const int bq = nt >> 1, of = (nt & 1) * 2;
                mma_f16(fr.acc[mt][nt], al[mt], bx[bq][of], bx[bq][of + 1]);
            }
    }
}

__device__ __forceinline__ void epilogue(const Frag& fr, float* C, const float* bias,
                                         size_t m0, size_t n0, int wm, int wn, int lane) {
    const int g  = lane >> 2;
    const int tc = lane & 3;
    #pragma unroll
    for (int mt = 0; mt < 2; mt++) {
        const size_t row0 = m0 + wm * 32 + mt * 16 + g;
        #pragma unroll
        for (int nt = 0; nt < 8; nt++) {
            const size_t col = n0 + wn * 64 + nt * 8 + tc * 2;
            float b0 = 0.0f, b1 = 0.0f;
            if (bias != nullptr) { b0 = bias[col]; b1 = bias[col + 1]; }
            float2 v0 = make_float2(fr.acc[mt][nt][0] + b0, fr.acc[mt][nt][1] + b1);
            float2 v1 = make_float2(fr.acc[mt][nt][2] + b0, fr.acc[mt][nt][3] + b1);
            *(float2*)(C + row0 * DD + col)       = v0;
            *(float2*)(C + (row0 + 8) * DD + col) = v1;
        }
    }
}

// ============================================================================
// gout GEMM (fp16 2-pass): A = y hi/lo fp16, B = w_out fp16 (hi only).
// Stage 24KB: Ahi@0, Alo@8K, Bh@16K. 3 stages = 72KB, 2 CTAs/SM.
// Single barrier per tile.
// ============================================================================
#define GO_STAGE 24576

__global__ __launch_bounds__(256, 2)
void gemm_f16_kernel(const __half* __restrict__ Ahi, const __half* __restrict__ Alo,
                     const __half* __restrict__ Bh,
                     float* __restrict__ C, int s_base) {
    extern __shared__ __align__(128) char smem[];
    const uint32_t sb = smem_u32(smem);

    const int t    = threadIdx.x;
    const int lane = t & 31;
    const int wid  = t >> 5;
    const int wm   = wid >> 1;
    const int wn   = wid & 1;
    const size_t m0 = (size_t)blockIdx.z * SS + (size_t)s_base + (size_t)blockIdx.y * 128;
    const size_t n0 = (size_t)blockIdx.x * 128;

    const int ar = t >> 2, ac = t & 3;
    const int br = t >> 4, bc = t & 15;
    const __half* pAh = Ahi + (m0 + ar) * DD + ac * 8;
    const __half* pAl = Alo + (m0 + ar) * DD + ac * 8;
    const __half* pBh = Bh + (size_t)br * DD + n0 + bc * 8;
    const uint32_t sA0 = aoff(ar, ac);
    const uint32_t sA1 = aoff(ar + 64, ac);
    const uint32_t sB0 = 16384 + boff(br, bc);
    const uint32_t sB1 = 16384 + boff(br + 16, bc);

    const int arow = wm * 32 + (lane & 7) + ((lane >> 3) & 1) * 8;
    const int akh  = (lane >> 4) & 1;
    uint32_t aAo[2][2];
    #pragma unroll
    for (int mt = 0; mt < 2; mt++)
        #pragma unroll
        for (int ks = 0; ks < 2; ks++)
            aAo[mt][ks] = aoff(arow + mt * 16, ks * 2 + akh);
    const int bpair = lane >> 4;
    const int bkr0  = ((lane >> 3) & 1) * 8 + (lane & 7);
    uint32_t aBo[2][4];
    #pragma unroll
    for (int ks = 0; ks < 2; ks++)
        #pragma unroll
        for (int bq = 0; bq < 4; bq++)
            aBo[ks][bq] = 16384 + boff(ks * 16 + bkr0, wn * 8 + bq * 2 + bpair);

    Frag fr;
    #pragma unroll
    for (int mt = 0; mt < 2; mt++)
        #pragma unroll
        for (int nt = 0; nt < 8; nt++)
            #pragma unroll
            for (int i = 0; i < 4; i++) fr.acc[mt][nt][i] = 0.0f;

    auto load_stage = [&](int stg, int k0) {
        const uint32_t s = sb + (uint32_t)stg * GO_STAGE;
        cp_async16(s + sA0, pAh + k0);
        cp_async16(s + sA1, pAh + (size_t)64 * DD + k0);
        cp_async16(s + sA0 + 8192, pAl + k0);
        cp_async16(s + sA1 + 8192, pAl + (size_t)64 * DD + k0);
        cp_async16(s + sB0, pBh + (size_t)k0 * DD);
        cp_async16(s + sB1, pBh + (size_t)(k0 + 16) * DD);
    };

    load_stage(0, 0);
    asm volatile("cp.async.commit_group;" ::: "memory");
    load_stage(1, 32);
    asm volatile("cp.async.commit_group;" ::: "memory");

    for (int tile = 0; tile < 64; tile++) {
        asm volatile("cp.async.wait_group 1;" ::: "memory");
        __syncthreads();
        if (tile + 2 < 64) load_stage((tile + 2) % 3, (tile + 2) * 32);
        asm volatile("cp.async.commit_group;" ::: "memory");

        const uint32_t stg = sb + (uint32_t)(tile % 3) * GO_STAGE;
        mma_tile_f16(fr, stg, stg, aAo, aBo);
    }

    epilogue(fr, C, nullptr, m0, n0, wm, wn, lane);
}

// ============================================================================
// gin hybrid GEMM (3-pass bf16, known accuracy): A = raw fp32 input
// (LDG -> hi/lo cvt -> STS, double-buffered), B = pre-split bf16 w_in via
// 3-stage cp.async. Single barrier per tile. 80KB, 2 CTAs/SM.
// ============================================================================
#define HB_ABUF 16384
#define HB_BBASE 32768
#define HB_BSTG 16384

__global__ __launch_bounds__(256, 2)
void gemm_hybrid_kernel(const float* __restrict__ A,
                        const __nv_bfloat16* __restrict__ Bhi, const __nv_bfloat16* __restrict__ Blo,
                        const float* __restrict__ bias, float* __restrict__ C, int s_base) {
    extern __shared__ __align__(128) char smem[];
    const uint32_t sb = smem_u32(smem);

    const int t    = threadIdx.x;
    const int lane = t & 31;
    const int wid  = t >> 5;
    const int wm   = wid >> 1;
    const int wn   = wid & 1;
    const size_t m0 = (size_t)blockIdx.z * SS + (size_t)s_base + (size_t)blockIdx.y * 128;
    const size_t n0 = (size_t)blockIdx.x * 128;

    const int ar = t >> 2, ac = t & 3;
    const int br = t >> 4, bc = t & 15;
    const float* pA = A + (m0 + ar) * DD + ac * 8;   // fp32
    const __nv_bfloat16* pBh = Bhi + (size_t)br * DD + n0 + bc * 8;
    const __nv_bfloat16* pBl = Blo + (size_t)br * DD + n0 + bc * 8;
    const uint32_t sA0 = aoff(ar, ac);
    const uint32_t sA1 = aoff(ar + 64, ac);
    const uint32_t sB0 = HB_BBASE + boff(br, bc);
    const uint32_t sB1 = HB_BBASE + boff(br + 16, bc);

    const int arow = wm * 32 + (lane & 7) + ((lane >> 3) & 1) * 8;
    const int akh  = (lane >> 4) & 1;
    uint32_t aAo[2][2];
    #pragma unroll
    for (int mt = 0; mt < 2; mt++)
        #pragma unroll
        for (int ks = 0; ks < 2; ks++)
            aAo[mt][ks] = aoff(arow + mt * 16, ks * 2 + akh);
    const int bpair = lane >> 4;
    const int bkr0  = ((lane >> 3) & 1) * 8 + (lane & 7);
    uint32_t aBo[2][4];
    #pragma unroll
    for (int ks = 0; ks < 2; ks++)
        #pragma unroll
        for (int bq = 0; bq < 4; bq++)
            aBo[ks][bq] = boff(ks * 16 + bkr0, wn * 8 + bq * 2 + bpair);

    Frag fr;
    #pragma unroll
    for (int mt = 0; mt < 2; mt++)
        #pragma unroll
        for (int nt = 0; nt < 8; nt++)
            #pragma unroll
            for (int i = 0; i < 4; i++) fr.acc[mt][nt][i] = 0.0f;

    auto load_b_stage = [&](int stg, int k0) {
        const uint32_t off = (uint32_t)stg * HB_BSTG;
        cp_async16(sb + sB0 + off, pBh + (size_t)k0 * DD);
        cp_async16(sb + sB1 + off, pBh + (size_t)(k0 + 16) * DD);
        cp_async16(sb + sB0 + off + 8192, pBl + (size_t)k0 * DD);
        cp_async16(sb + sB1 + off + 8192, pBl + (size_t)(k0 + 16) * DD);
    };

    // ---- prologue ----
    float4 rA0a = *(const float4*)(pA);
    float4 rA0b = *(const float4*)(pA + 4);
    float4 rA1a = *(const float4*)(pA + (size_t)64 * DD);
    float4 rA1b = *(const float4*)(pA + (size_t)64 * DD + 4);
    load_b_stage(0, 0);
    asm volatile("cp.async.commit_group;" ::: "memory");
    load_b_stage(1, 32);
    asm volatile("cp.async.commit_group;" ::: "memory");
    cvt_store(sb + sA0, sb + sA0 + 8192, rA0a, rA0b);
    cvt_store(sb + sA1, sb + sA1 + 8192, rA1a, rA1b);
    rA0a = *(const float4*)(pA + 32);
    rA0b = *(const float4*)(pA + 36);
    rA1a = *(const float4*)(pA + (size_t)64 * DD + 32);
    rA1b = *(const float4*)(pA + (size_t)64 * DD + 36);

    for (int tile = 0; tile < 64; tile++) {
        asm volatile("cp.async.wait_group 1;" ::: "memory");
        __syncthreads();
        if (tile + 2 < 64) load_b_stage((tile + 2) % 3, (tile + 2) * 32);
        asm volatile("cp.async.commit_group;" ::: "memory");

        const uint32_t abuf = sb + (uint32_t)(tile & 1) * HB_ABUF;
        const uint32_t bstg = sb + HB_BBASE + (uint32_t)(tile % 3) * HB_BSTG;
        mma_tile(fr, abuf, bstg, aAo, aBo);

        if (tile + 1 < 64) {
            const uint32_t nbuf = sb + (uint32_t)((tile + 1) & 1) * HB_ABUF;
            cvt_store(nbuf + sA0, nbuf + sA0 + 8192, rA0a, rA0b);
            cvt_store(nbuf + sA1, nbuf + sA1 + 8192, rA1a, rA1b);
            if (tile + 2 < 64) {
                const float* p = pA + (size_t)(tile + 2) * 32;
                rA0a = *(const float4*)(p);
                rA0b = *(const float4*)(p + 4);
                rA1a = *(const float4*)(p + (size_t)64 * DD);
                rA1b = *(const float4*)(p + (size_t)64 * DD + 4);
            }
        }
    }

    epilogue(fr, C, bias, m0, n0, wm, wn, lane);
}

// ============================================================================
// Scan chunk: TWO independent heads per CTA (256 thr; head = tid>>7).
// Emits y as fp16 hi/lo for the 2-pass gout GEMM. One barrier per step.
// ============================================================================
__global__ __launch_bounds__(256, 1)
void scan_kernel(const float* __restrict__ x, const float* __restrict__ sin,
                 const float* __restrict__ SW,
                 __half* __restrict__ yhi, __half* __restrict__ ylo,
                 float* __restrict__ sfin, int s_base, int s_len) {
    const int b    = blockIdx.x >> 3;
    const int np   = blockIdx.x & 7;
    const int head = threadIdx.x >> 7;
    const int k    = threadIdx.x & 127;
    const int n    = np * 2 + head;

    const float* Wn = SW + (size_t)n * HH * HH;
    ull w2[64];
    #pragma unroll
    for (int j = 0; j < 64; j++)
        w2[j] = pack2(Wn[(2 * j) * HH + k], Wn[(2 * j + 1) * HH + k]);

    __shared__ __align__(16) float sbuf[2][2][HH];   // [buf][head][k]
    sbuf[0][head][k] = sin[((size_t)b * NH + n) * HH + k];
    __syncthreads();

    const float* xp = x + ((size_t)b * SS + s_base) * DD + n * HH + k;
    __half* yhp = yhi + ((size_t)b * SS + s_base) * DD + n * HH + k;
    __half* ylp = ylo + ((size_t)b * SS + s_base) * DD + n * HH + k;

    float xa = xp[0];
    float xb = xp[DD];
    float xc = xp[2 * (size_t)DD];
    float v = 0.0f;

    for (int t = 0; t < s_len; t++) {
        float xn = 0.0f;
        if (t + 3 < s_len) xn = xp[(size_t)(t + 3) * DD];

        const ulonglong2* s4 = (const ulonglong2*)sbuf[t & 1][head];
        ull a0 = 0ull, a1 = 0ull, a2 = 0ull, a3 = 0ull;
        ull a4 = 0ull, a5 = 0ull, a6 = 0ull, a7 = 0ull;
        #pragma unroll
        for (int j = 0; j < 8; j++) {
            ulonglong2 p = s4[4 * j];
            ulonglong2 q = s4[4 * j + 1];
            ulonglong2 r = s4[4 * j + 2];
            ulonglong2 s = s4[4 * j + 3];
            a0 = ffma2(p.x, w2[8 * j + 0], a0);
            a1 = ffma2(p.y, w2[8 * j + 1], a1);
            a2 = ffma2(q.x, w2[8 * j + 2], a2);
            a3 = ffma2(q.y, w2[8 * j + 3], a3);
            a4 = ffma2(r.x, w2[8 * j + 4], a4);
            a5 = ffma2(r.y, w2[8 * j + 5], a5);
            a6 = ffma2(s.x, w2[8 * j + 6], a6);
            a7 = ffma2(s.y, w2[8 * j + 7], a7);
        }
        ull s01 = addf2(a0, a1), s23 = addf2(a2, a3);
        ull s45 = addf2(a4, a5), s67 = addf2(a6, a7);
        ull sall = addf2(addf2(s01, s23), addf2(s45, s67));
        float lo, hi;
        unpack2(sall, lo, hi);
        float dot = lo + hi;

        v = fast_tanh(dot + xa);
        __half h = __float2half_rn(v);
        yhp[(size_t)t * DD] = h;
        ylp[(size_t)t * DD] = __float2half_rn(v - __half2float(h));
        sbuf[(t + 1) & 1][head][k] = v;

        xa = xb; xb = xc; xc = xn;
        __syncthreads();
    }

    sfin[((size_t)b * NH + n) * HH + k] = v;
}

// ============================================================================
// Launch: minimal prelude + 3-stream chunked pipeline.
//   origin: gin_c x8 (hybrid bf16 3-pass)
//   st1 (hi prio): w_out fp16 cvt, then scan_c x8
//   st2: w_in bf16 split (gates gins), then gout_c x8 (fp16 2-pass)
// ============================================================================
extern "C" void kernel_launch(void* const* d_in, const int* in_sizes, int n_in,
                              void* d_out, int out_size) {
    const float* input  = (const float*)d_in[0];
    const float* state0 = (const float*)d_in[1];
    const float* w_in   = (const float*)d_in[2];
    const float* b_in   = (const float*)d_in[3];
    const float* sw     = (const float*)d_in[4];
    const float* w_out  = (const float*)d_in[5];
    float* out = (float*)d_out;

    float *xbuf, *stbuf;
    __half *yhi, *ylo, *woh;
    __nv_bfloat16 *wihi, *wilo;
    cudaGetSymbolAddress((void**)&xbuf, g_x);
    cudaGetSymbolAddress((void**)&stbuf, g_state);
    cudaGetSymbolAddress((void**)&yhi, g_yhi);
    cudaGetSymbolAddress((void**)&ylo, g_ylo);
    cudaGetSymbolAddress((void**)&wihi, g_wihi);
    cudaGetSymbolAddress((void**)&wilo, g_wilo);
    cudaGetSymbolAddress((void**)&woh, g_woh);

    static cudaStream_t st1 = nullptr, st2 = nullptr;
    static cudaEvent_t ev_gin[NCH], ev_scan[NCH], ev_root, ev_w, ev_tail;
    if (st1 == nullptr) {
        int prio_lo, prio_hi;
        cudaDeviceGetStreamPriorityRange(&prio_lo, &prio_hi);
        cudaStreamCreateWithPriority(&st1, cudaStreamNonBlocking, prio_hi);  // scan: highest
        cudaStreamCreateWithFlags(&st2, cudaStreamNonBlocking);
        for (int c = 0; c < NCH; c++) {
            cudaEventCreateWithFlags(&ev_gin[c], cudaEventDisableTiming);
            cudaEventCreateWithFlags(&ev_scan[c], cudaEventDisableTiming);
        }
        cudaEventCreateWithFlags(&ev_root, cudaEventDisableTiming);
        cudaEventCreateWithFlags(&ev_w, cudaEventDisableTiming);
        cudaEventCreateWithFlags(&ev_tail, cudaEventDisableTiming);
    }

    const int smem_gout = 3 * GO_STAGE;               // 73728
    const int smem_gin  = 2 * HB_ABUF + 3 * HB_BSTG;  // 81920
    cudaFuncSetAttribute(gemm_f16_kernel, cudaFuncAttributeMaxDynamicSharedMemorySize, smem_gout);
    cudaFuncSetAttribute(gemm_hybrid_kernel, cudaFuncAttributeMaxDynamicSharedMemorySize, smem_gin);

    // ---- prelude: w_out fp16 cvt on st1 (hidden), w_in bf16 split on st2 (gates gins) ----
    cudaEventRecord(ev_root, 0);
    cudaStreamWaitEvent(st1, ev_root, 0);
    cvt_f16_kernel<<<4096, 256, 0, st1>>>(w_out, woh, DD * DD / 4);
    cudaStreamWaitEvent(st2, ev_root, 0);
    cvt_split_kernel<<<4096, 256, 0, st2>>>(w_in, wihi, wilo, DD * DD / 4);
    cudaEventRecord(ev_w, st2);
    cudaStreamWaitEvent(0, ev_w, 0);

    dim3 ggrid(DD / 128, CH / 128, BB);  // (16, 4, 4) = 256 CTAs per chunk

    // Input-projection chunks (hybrid, reads fp32 input directly) on origin
    for (int c = 0; c < NCH; c++) {
        gemm_hybrid_kernel<<<ggrid, 256, smem_gin>>>(input, wihi, wilo, b_in, xbuf, c * CH);
        cudaEventRecord(ev_gin[c], 0);
    }

    // Scan chunks on high-priority stream (sequential by state dependency)
    for (int c = 0; c < NCH; c++) {
        cudaStreamWaitEvent(st1, ev_gin[c], 0);
        const float* s_init = (c == 0) ? state0 : stbuf;
        scan_kernel<<<BB * NH / 2, 256, 0, st1>>>(xbuf, s_init, sw, yhi, ylo, stbuf, c * CH, CH);
        cudaEventRecord(ev_scan[c], st1);
    }

    // Output-projection chunks on st2 (fp16 2-pass)
    for (int c = 0; c < NCH; c++) {
        cudaStreamWaitEvent(st2, ev_scan[c], 0);
        gemm_f16_kernel<<<ggrid, 256, smem_gout, st2>>>(yhi, ylo, woh, out, c * CH);
    }

    // Join forked work back to origin stream for graph capture
    cudaEventRecord(ev_tail, st2);
    cudaStreamWaitEvent(0, ev_tail, 0);
}